// round 1
// baseline (speedup 1.0000x reference)
#include <cuda_runtime.h>
#include <math.h>

// Problem constants
#define BB   8
#define CC   256
#define NN   4096          // H*W
#define KK   1024          // top-K
#define NH   8
#define HD   32
#define CH   64            // importance hidden

// ---------------- scratch (device globals; no allocation) ----------------
__device__ float g_imp  [BB * NN];
__device__ int   g_topidx[BB * KK];
__device__ int   g_pos2k [BB * NN];
__device__ float g_xsp  [BB * KK * CC];
__device__ float g_q    [BB * KK * CC];
__device__ float g_k    [BB * KK * CC];
__device__ float g_v    [BB * KK * CC];
__device__ float g_ao   [BB * KK * CC];
__device__ float g_ps   [BB * KK * CC];
__device__ float g_enh  [BB * KK * CC];

// ---------------- kernel 1: importance net ----------------
// h = gelu(W1 x + b1); imp = sigmoid(w2 h + b2) + 0.5*boundary
// one thread per pixel; w1 chunk transposed into smem for float4 broadcast reads
__global__ void importance_kernel(const float* __restrict__ x,
                                  const float* __restrict__ bmap,
                                  const float* __restrict__ w1,
                                  const float* __restrict__ b1,
                                  const float* __restrict__ w2,
                                  const float* __restrict__ b2,
                                  float* __restrict__ imp,
                                  float* __restrict__ imp_out)
{
    __shared__ float wsT[64][68];  // [c-in-chunk][j], stride 68 (16B aligned rows)
    int tid = threadIdx.x;
    int b = blockIdx.x >> 4;
    int p = ((blockIdx.x & 15) << 8) + tid;

    float hacc[CH];
#pragma unroll
    for (int j = 0; j < CH; j++) hacc[j] = b1[j];

    for (int c0 = 0; c0 < CC; c0 += 64) {
        __syncthreads();
        // load w1[:, c0:c0+64] transposed
        for (int f = tid; f < 1024; f += 256) {
            int j  = f >> 4;
            int cb = (f & 15) * 4;
            float4 v = *(const float4*)(w1 + j * CC + c0 + cb);
            wsT[cb + 0][j] = v.x; wsT[cb + 1][j] = v.y;
            wsT[cb + 2][j] = v.z; wsT[cb + 3][j] = v.w;
        }
        __syncthreads();
#pragma unroll 8
        for (int cc = 0; cc < 64; cc++) {
            float xv = x[((size_t)(b * CC + c0 + cc) << 12) + p];
            const float4* wp = (const float4*)wsT[cc];
#pragma unroll
            for (int j4 = 0; j4 < 16; j4++) {
                float4 w4 = wp[j4];
                hacc[j4 * 4 + 0] += w4.x * xv;
                hacc[j4 * 4 + 1] += w4.y * xv;
                hacc[j4 * 4 + 2] += w4.z * xv;
                hacc[j4 * 4 + 3] += w4.w * xv;
            }
        }
    }
    float acc = b2[0];
#pragma unroll
    for (int j = 0; j < CH; j++) {
        float v = hacc[j];
        float ge = 0.5f * v * (1.0f + erff(v * 0.70710678118654752f));
        acc += ge * w2[j];
    }
    float sg  = 1.0f / (1.0f + __expf(-acc));
    float val = sg + 0.5f * bmap[(b << 12) + p];
    imp[(b << 12) + p] = val;
    if (imp_out) imp_out[(b << 12) + p] = val;
}

// ---------------- kernel 2: exact top-K via bitonic sort ----------------
// composite key: (float_bits<<32) | (4095-idx)  -> descending sort gives
// jax top_k semantics (value desc, lower index wins ties). Then sort the
// 1024 winning indices ascending for gather locality; build pos->k map.
__global__ void topk_kernel(const float* __restrict__ imp,
                            int* __restrict__ topidx,
                            int* __restrict__ pos2k)
{
    __shared__ unsigned long long keys[NN];
    __shared__ int idxs[KK];
    int tid = threadIdx.x;  // 1024
    int b = blockIdx.x;

    for (int i = tid; i < NN; i += 1024) {
        unsigned int fb = __float_as_uint(imp[(b << 12) + i]);
        keys[i] = ((unsigned long long)fb << 32) | (unsigned int)(NN - 1 - i);
        pos2k[(b << 12) + i] = -1;
    }
    __syncthreads();

    // bitonic sort, descending
    for (int k2 = 2; k2 <= NN; k2 <<= 1) {
        for (int j = k2 >> 1; j > 0; j >>= 1) {
            for (int t = tid; t < NN; t += 1024) {
                int ixj = t ^ j;
                if (ixj > t) {
                    unsigned long long a = keys[t], c = keys[ixj];
                    if ((a < c) == ((t & k2) == 0)) { keys[t] = c; keys[ixj] = a; }
                }
            }
            __syncthreads();
        }
    }
    idxs[tid] = (NN - 1) - (int)(keys[tid] & 0xFFFFFFFFull);
    __syncthreads();
    // ascending sort of winning indices
    for (int k2 = 2; k2 <= KK; k2 <<= 1) {
        for (int j = k2 >> 1; j > 0; j >>= 1) {
            int ixj = tid ^ j;
            if (ixj > tid) {
                int a = idxs[tid], c = idxs[ixj];
                if ((a > c) == ((tid & k2) == 0)) { idxs[tid] = c; idxs[ixj] = a; }
            }
            __syncthreads();
        }
    }
    int p = idxs[tid];
    topidx[(b << 10) + tid] = p;
    pos2k[(b << 12) + p] = tid;
}

// ---------------- kernel 3: gather x_sp[b,k,c] = x[b,c,idx[b,k]] ----------------
__global__ void gather_kernel(const float* __restrict__ x,
                              const int* __restrict__ topidx,
                              float* __restrict__ xsp)
{
    int gid = blockIdx.x * 256 + threadIdx.x;   // < B*K*C = 2097152
    int b = gid >> 18;
    int k = (gid >> 8) & (KK - 1);
    int c = gid & (CC - 1);
    int p = topidx[(b << 10) + k];
    xsp[gid] = x[((size_t)((b << 8) + c) << 12) + p];
}

// ---------------- kernel 4: GEMM  C[m,n] = sum_c A[m,c]*W[n,c] + bias[n] ----------------
#define GBM 128
#define GBN 64
#define GBK 16
__global__ void gemm_bias_kernel(const float* __restrict__ A,
                                 const float* __restrict__ W,
                                 const float* __restrict__ bias,
                                 float* __restrict__ Cout,
                                 int M, int Nn, int Kd)
{
    __shared__ float As[GBK][132];  // [c][m], row stride 132 (16B aligned)
    __shared__ float Ws[GBK][68];   // [c][n]
    int tid = threadIdx.x;          // 256
    int bm = blockIdx.y * GBM;
    int bn = blockIdx.x * GBN;
    int tx = tid & 15, ty = tid >> 4;

    float acc[8][4];
#pragma unroll
    for (int i = 0; i < 8; i++)
#pragma unroll
        for (int j = 0; j < 4; j++) acc[i][j] = 0.f;

    for (int c0 = 0; c0 < Kd; c0 += GBK) {
#pragma unroll
        for (int i = 0; i < 2; i++) {            // A tile: 128x16 = 512 float4
            int f = tid + i * 256;
            int m = f >> 2;
            int cb = (f & 3) * 4;
            float4 v = *(const float4*)(A + (size_t)(bm + m) * Kd + c0 + cb);
            As[cb + 0][m] = v.x; As[cb + 1][m] = v.y;
            As[cb + 2][m] = v.z; As[cb + 3][m] = v.w;
        }
        {                                         // W tile: 64x16 = 256 float4
            int n = tid >> 2;
            int cb = (tid & 3) * 4;
            float4 v = *(const float4*)(W + (size_t)(bn + n) * Kd + c0 + cb);
            Ws[cb + 0][n] = v.x; Ws[cb + 1][n] = v.y;
            Ws[cb + 2][n] = v.z; Ws[cb + 3][n] = v.w;
        }
        __syncthreads();
#pragma unroll
        for (int cc = 0; cc < GBK; cc++) {
            float a[8], w[4];
            *(float4*)&a[0] = *(const float4*)&As[cc][ty * 8];
            *(float4*)&a[4] = *(const float4*)&As[cc][ty * 8 + 4];
            *(float4*)&w[0] = *(const float4*)&Ws[cc][tx * 4];
#pragma unroll
            for (int i = 0; i < 8; i++)
#pragma unroll
                for (int j = 0; j < 4; j++) acc[i][j] += a[i] * w[j];
        }
        __syncthreads();
    }
#pragma unroll
    for (int i = 0; i < 8; i++) {
        int m = bm + ty * 8 + i;
#pragma unroll
        for (int j = 0; j < 4; j++) {
            int n = bn + tx * 4 + j;
            Cout[(size_t)m * Nn + n] = acc[i][j] + bias[n];
        }
    }
}

// ---------------- kernel 5: flash attention (fp32, online softmax) ----------------
// grid (K/128, NH, B), 128 threads, thread per query row. BLOCK_N = 64.
#define ABM 128
#define ABN 64
__global__ void attn_kernel(const float* __restrict__ Q,
                            const float* __restrict__ Kb,
                            const float* __restrict__ Vb,
                            float* __restrict__ O)
{
    __shared__ float KV[ABN][HD];     // K tile then V tile (reused)
    __shared__ float Ss[ABM][65];     // scores, stride 65 (conflict-free)
    int tid = threadIdx.x;
    int m0 = blockIdx.x * ABM;
    int hh = blockIdx.y;
    int b  = blockIdx.z;
    size_t base = (size_t)b * KK * CC + hh * HD;
    const float scale = 0.17677669529663687f;  // 1/sqrt(32)

    float q[HD];
    {
        const float* qp = Q + base + (size_t)(m0 + tid) * CC;
#pragma unroll
        for (int d4 = 0; d4 < 8; d4++) {
            float4 v = *(const float4*)(qp + d4 * 4);
            q[d4 * 4 + 0] = v.x; q[d4 * 4 + 1] = v.y;
            q[d4 * 4 + 2] = v.z; q[d4 * 4 + 3] = v.w;
        }
    }
    float mmax = -INFINITY, l = 0.f;
    float o[HD];
#pragma unroll
    for (int d = 0; d < HD; d++) o[d] = 0.f;

    for (int n0 = 0; n0 < KK; n0 += ABN) {
        __syncthreads();   // protect KV from previous iteration's readers
        for (int e = tid; e < ABN * 8; e += 128) {   // K tile (512 float4)
            int j = e >> 3, d4 = e & 7;
            *(float4*)&KV[j][d4 * 4] =
                *(const float4*)(Kb + base + (size_t)(n0 + j) * CC + d4 * 4);
        }
        __syncthreads();

        float tmax = -INFINITY;
#pragma unroll 4
        for (int j = 0; j < ABN; j++) {
            const float4* kp = (const float4*)KV[j];
            float s = 0.f;
#pragma unroll
            for (int d4 = 0; d4 < 8; d4++) {
                float4 kv = kp[d4];
                s += q[d4 * 4 + 0] * kv.x + q[d4 * 4 + 1] * kv.y
                   + q[d4 * 4 + 2] * kv.z + q[d4 * 4 + 3] * kv.w;
            }
            s *= scale;
            Ss[tid][j] = s;
            tmax = fmaxf(tmax, s);
        }
        __syncthreads();
        for (int e = tid; e < ABN * 8; e += 128) {   // V tile
            int j = e >> 3, d4 = e & 7;
            *(float4*)&KV[j][d4 * 4] =
                *(const float4*)(Vb + base + (size_t)(n0 + j) * CC + d4 * 4);
        }
        __syncthreads();

        float mnew = fmaxf(mmax, tmax);
        float corr = __expf(mmax - mnew);
        l *= corr;
#pragma unroll
        for (int d = 0; d < HD; d++) o[d] *= corr;
#pragma unroll 4
        for (int j = 0; j < ABN; j++) {
            float p = __expf(Ss[tid][j] - mnew);
            l += p;
            const float4* vp = (const float4*)KV[j];
#pragma unroll
            for (int d4 = 0; d4 < 8; d4++) {
                float4 vv = vp[d4];
                o[d4 * 4 + 0] += p * vv.x; o[d4 * 4 + 1] += p * vv.y;
                o[d4 * 4 + 2] += p * vv.z; o[d4 * 4 + 3] += p * vv.w;
            }
        }
        mmax = mnew;
    }
    float inv = 1.0f / l;
    float* op = O + base + (size_t)(m0 + tid) * CC;
#pragma unroll
    for (int d4 = 0; d4 < 8; d4++) {
        float4 v;
        v.x = o[d4 * 4 + 0] * inv; v.y = o[d4 * 4 + 1] * inv;
        v.z = o[d4 * 4 + 2] * inv; v.w = o[d4 * 4 + 3] * inv;
        *(float4*)(op + d4 * 4) = v;
    }
}

// ---------------- kernel 6: residual + LayerNorm ----------------
__global__ void ln_kernel(const float* __restrict__ P,
                          const float* __restrict__ X,
                          const float* __restrict__ g,
                          const float* __restrict__ beta,
                          float* __restrict__ E)
{
    int row = blockIdx.x;
    int c = threadIdx.x;   // 256
    size_t off = (size_t)row * CC + c;
    float y = P[off] + X[off];
    float v1 = y, v2 = y * y;
#pragma unroll
    for (int o = 16; o > 0; o >>= 1) {
        v1 += __shfl_xor_sync(0xffffffff, v1, o);
        v2 += __shfl_xor_sync(0xffffffff, v2, o);
    }
    __shared__ float s1[8], s2[8];
    int w = c >> 5, ln = c & 31;
    if (ln == 0) { s1[w] = v1; s2[w] = v2; }
    __syncthreads();
    float sum = 0.f, sq = 0.f;
#pragma unroll
    for (int i = 0; i < 8; i++) { sum += s1[i]; sq += s2[i]; }
    float mu  = sum * (1.0f / CC);
    float var = sq * (1.0f / CC) - mu * mu;
    float rs  = rsqrtf(var + 1e-5f);
    E[off] = (y - mu) * rs * g[c] + beta[c];
}

// ---------------- kernel 7: copy x -> out, overlay enhanced tokens ----------------
__global__ void scatter_kernel(const float* __restrict__ X,
                               const int* __restrict__ pos2k,
                               const float* __restrict__ E,
                               float* __restrict__ out)
{
    int gid = blockIdx.x * 256 + threadIdx.x;   // < B*C*N = 8388608
    int b = gid >> 20;
    int c = (gid >> 12) & (CC - 1);
    int p = gid & (NN - 1);
    int k = pos2k[(b << 12) + p];
    float v = (k >= 0) ? E[(size_t)(((b << 10) + k) << 8) + c] : X[gid];
    out[gid] = v;
}

// ---------------- launch ----------------
extern "C" void kernel_launch(void* const* d_in, const int* in_sizes, int n_in,
                              void* d_out, int out_size)
{
    const float* x    = (const float*)d_in[0];
    const float* bmap = (const float*)d_in[1];
    const float* iw1  = (const float*)d_in[2];
    const float* ib1  = (const float*)d_in[3];
    const float* iw2  = (const float*)d_in[4];
    const float* ib2  = (const float*)d_in[5];
    const float* wq   = (const float*)d_in[6];
    const float* bq   = (const float*)d_in[7];
    const float* wk   = (const float*)d_in[8];
    const float* bk   = (const float*)d_in[9];
    const float* wv   = (const float*)d_in[10];
    const float* bv   = (const float*)d_in[11];
    const float* wo   = (const float*)d_in[12];
    const float* bo   = (const float*)d_in[13];
    const float* lng  = (const float*)d_in[14];
    const float* lnb  = (const float*)d_in[15];

    // lazy-cached scratch addresses (resolved on the correctness call,
    // so no runtime API calls happen during graph capture)
    static float *P_imp = nullptr, *P_xsp, *P_q, *P_k, *P_v, *P_ao, *P_ps, *P_enh;
    static int *P_topidx, *P_pos2k;
    if (!P_imp) {
        cudaGetSymbolAddress((void**)&P_imp,    g_imp);
        cudaGetSymbolAddress((void**)&P_topidx, g_topidx);
        cudaGetSymbolAddress((void**)&P_pos2k,  g_pos2k);
        cudaGetSymbolAddress((void**)&P_xsp,    g_xsp);
        cudaGetSymbolAddress((void**)&P_q,      g_q);
        cudaGetSymbolAddress((void**)&P_k,      g_k);
        cudaGetSymbolAddress((void**)&P_v,      g_v);
        cudaGetSymbolAddress((void**)&P_ao,     g_ao);
        cudaGetSymbolAddress((void**)&P_ps,     g_ps);
        cudaGetSymbolAddress((void**)&P_enh,    g_enh);
    }

    float* out = (float*)d_out;
    float* imp_out = (out_size >= BB * CC * NN + BB * NN) ? out + (size_t)BB * CC * NN
                                                          : nullptr;

    importance_kernel<<<BB * (NN / 256), 256>>>(x, bmap, iw1, ib1, iw2, ib2,
                                                P_imp, imp_out);
    topk_kernel<<<BB, 1024>>>(P_imp, P_topidx, P_pos2k);
    gather_kernel<<<(BB * KK * CC) / 256, 256>>>(x, P_topidx, P_xsp);

    dim3 ggrid(CC / GBN, (BB * KK) / GBM);   // (4, 64)
    gemm_bias_kernel<<<ggrid, 256>>>(P_xsp, wq, bq, P_q, BB * KK, CC, CC);
    gemm_bias_kernel<<<ggrid, 256>>>(P_xsp, wk, bk, P_k, BB * KK, CC, CC);
    gemm_bias_kernel<<<ggrid, 256>>>(P_xsp, wv, bv, P_v, BB * KK, CC, CC);

    dim3 agrid(KK / ABM, NH, BB);            // (8, 8, 8)
    attn_kernel<<<agrid, 128>>>(P_q, P_k, P_v, P_ao);

    gemm_bias_kernel<<<ggrid, 256>>>(P_ao, wo, bo, P_ps, BB * KK, CC, CC);

    ln_kernel<<<BB * KK, 256>>>(P_ps, P_xsp, lng, lnb, P_enh);
    scatter_kernel<<<(BB * CC * NN) / 256, 256>>>(x, P_pos2k, P_enh, out);
}

// round 4
// speedup vs baseline: 1.5511x; 1.5511x over previous
#include <cuda_runtime.h>
#include <math.h>

// Problem constants
#define BB   8
#define CC   256
#define NN   4096          // H*W
#define KK   1024          // top-K
#define NH   8
#define HD   32
#define CH   64            // importance hidden

// ---------------- scratch (device globals; no allocation) ----------------
__device__ float g_imp  [BB * NN];
__device__ int   g_topidx[BB * KK];
__device__ int   g_pos2k [BB * NN];
__device__ float g_xsp  [BB * KK * CC];
__device__ float g_q    [BB * KK * CC];
__device__ float g_k    [BB * KK * CC];
__device__ float g_v    [BB * KK * CC];
__device__ float g_ao   [BB * KK * CC];
__device__ float g_ps   [BB * KK * CC];
__device__ float g_enh  [BB * KK * CC];

// ---------------- tf32 mma helpers ----------------
__device__ __forceinline__ void mma_tf32(float* d,
                                         unsigned a0, unsigned a1, unsigned a2, unsigned a3,
                                         unsigned b0, unsigned b1)
{
    asm volatile(
        "mma.sync.aligned.m16n8k8.row.col.f32.tf32.tf32.f32 "
        "{%0,%1,%2,%3}, {%4,%5,%6,%7}, {%8,%9}, {%0,%1,%2,%3};\n"
        : "+f"(d[0]), "+f"(d[1]), "+f"(d[2]), "+f"(d[3])
        : "r"(a0), "r"(a1), "r"(a2), "r"(a3), "r"(b0), "r"(b1));
}

// exact split: x = hi + lo, both exactly representable in tf32
__device__ __forceinline__ void tf32_split(float x, unsigned& hi, unsigned& lo)
{
    unsigned h = __float_as_uint(x) & 0xFFFFE000u;
    hi = h;
    lo = __float_as_uint(x - __uint_as_float(h));
}

// ---------------- kernel 1: importance net (exact fp32) ----------------
__global__ void importance_kernel(const float* __restrict__ x,
                                  const float* __restrict__ bmap,
                                  const float* __restrict__ w1,
                                  const float* __restrict__ b1,
                                  const float* __restrict__ w2,
                                  const float* __restrict__ b2,
                                  float* __restrict__ imp,
                                  float* __restrict__ imp_out)
{
    __shared__ float wsT[64][68];
    int tid = threadIdx.x;
    int b = blockIdx.x >> 4;
    int p = ((blockIdx.x & 15) << 8) + tid;

    float hacc[CH];
#pragma unroll
    for (int j = 0; j < CH; j++) hacc[j] = b1[j];

    for (int c0 = 0; c0 < CC; c0 += 64) {
        __syncthreads();
        for (int f = tid; f < 1024; f += 256) {
            int j  = f >> 4;
            int cb = (f & 15) * 4;
            float4 v = *(const float4*)(w1 + j * CC + c0 + cb);
            wsT[cb + 0][j] = v.x; wsT[cb + 1][j] = v.y;
            wsT[cb + 2][j] = v.z; wsT[cb + 3][j] = v.w;
        }
        __syncthreads();
#pragma unroll 8
        for (int cc = 0; cc < 64; cc++) {
            float xv = x[((size_t)(b * CC + c0 + cc) << 12) + p];
            const float4* wp = (const float4*)wsT[cc];
#pragma unroll
            for (int j4 = 0; j4 < 16; j4++) {
                float4 w4 = wp[j4];
                hacc[j4 * 4 + 0] += w4.x * xv;
                hacc[j4 * 4 + 1] += w4.y * xv;
                hacc[j4 * 4 + 2] += w4.z * xv;
                hacc[j4 * 4 + 3] += w4.w * xv;
            }
        }
    }
    float acc = b2[0];
#pragma unroll
    for (int j = 0; j < CH; j++) {
        float v = hacc[j];
        float ge = 0.5f * v * (1.0f + erff(v * 0.70710678118654752f));
        acc += ge * w2[j];
    }
    float sg  = 1.0f / (1.0f + __expf(-acc));
    float val = sg + 0.5f * bmap[(b << 12) + p];
    imp[(b << 12) + p] = val;
    if (imp_out) imp_out[(b << 12) + p] = val;
}

// ---------------- kernel 2: exact top-K via bitonic sort ----------------
__global__ void topk_kernel(const float* __restrict__ imp,
                            int* __restrict__ topidx,
                            int* __restrict__ pos2k)
{
    __shared__ unsigned long long keys[NN];
    __shared__ int idxs[KK];
    int tid = threadIdx.x;  // 1024
    int b = blockIdx.x;

    for (int i = tid; i < NN; i += 1024) {
        unsigned int fb = __float_as_uint(imp[(b << 12) + i]);
        keys[i] = ((unsigned long long)fb << 32) | (unsigned int)(NN - 1 - i);
        pos2k[(b << 12) + i] = -1;
    }
    __syncthreads();

    for (int k2 = 2; k2 <= NN; k2 <<= 1) {
        for (int j = k2 >> 1; j > 0; j >>= 1) {
            for (int t = tid; t < NN; t += 1024) {
                int ixj = t ^ j;
                if (ixj > t) {
                    unsigned long long a = keys[t], c = keys[ixj];
                    if ((a < c) == ((t & k2) == 0)) { keys[t] = c; keys[ixj] = a; }
                }
            }
            __syncthreads();
        }
    }
    idxs[tid] = (NN - 1) - (int)(keys[tid] & 0xFFFFFFFFull);
    __syncthreads();
    for (int k2 = 2; k2 <= KK; k2 <<= 1) {
        for (int j = k2 >> 1; j > 0; j >>= 1) {
            int ixj = tid ^ j;
            if (ixj > tid) {
                int a = idxs[tid], c = idxs[ixj];
                if ((a > c) == ((tid & k2) == 0)) { idxs[tid] = c; idxs[ixj] = a; }
            }
            __syncthreads();
        }
    }
    int p = idxs[tid];
    topidx[(b << 10) + tid] = p;
    pos2k[(b << 12) + p] = tid;
}

// ---------------- kernel 3: gather ----------------
__global__ void gather_kernel(const float* __restrict__ x,
                              const int* __restrict__ topidx,
                              float* __restrict__ xsp)
{
    int gid = blockIdx.x * 256 + threadIdx.x;
    int b = gid >> 18;
    int k = (gid >> 8) & (KK - 1);
    int c = gid & (CC - 1);
    int p = topidx[(b << 10) + k];
    xsp[gid] = x[((size_t)((b << 8) + c) << 12) + p];
}

// ---------------- kernel 4: tf32-split GEMM (C = A * W^T + bias) ----------------
// block tile 128x64, 256 threads (8 warps as 4x2), K-chunk 32.
// split-tf32: acc += ah*bh + ah*bl + al*bh  (fp32-accurate)
__global__ void gemm_tf32_kernel(const float* __restrict__ A,
                                 const float* __restrict__ W0, const float* __restrict__ B0, float* __restrict__ C0,
                                 const float* __restrict__ W1, const float* __restrict__ B1, float* __restrict__ C1,
                                 const float* __restrict__ W2, const float* __restrict__ B2, float* __restrict__ C2,
                                 int M, int Nn, int Kd)
{
    const float* W    = W0;
    const float* bias = B0;
    float*       Cout = C0;
    if (blockIdx.z == 1)      { W = W1; bias = B1; Cout = C1; }
    else if (blockIdx.z == 2) { W = W2; bias = B2; Cout = C2; }

    __shared__ float As[128 * 36];
    __shared__ float Ws[64 * 36];

    int tid  = threadIdx.x;
    int lane = tid & 31;
    int warp = tid >> 5;
    int wm = warp >> 1;           // 0..3 -> 32 rows
    int wn = warp & 1;            // 0..1 -> 32 cols
    int grp = lane >> 2;          // 0..7
    int tig = lane & 3;           // 0..3

    int bm = blockIdx.y * 128;
    int bn = blockIdx.x * 64;

    float acc[2][4][4];
#pragma unroll
    for (int mt = 0; mt < 2; mt++)
#pragma unroll
        for (int nt = 0; nt < 4; nt++)
#pragma unroll
            for (int j = 0; j < 4; j++) acc[mt][nt][j] = 0.f;

    for (int c0 = 0; c0 < Kd; c0 += 32) {
        // A tile: 128x32 (1024 float4)
#pragma unroll
        for (int i = 0; i < 4; i++) {
            int idx = tid + i * 256;
            int r = idx >> 3, c4 = (idx & 7) * 4;
            float4 v = *(const float4*)(A + (size_t)(bm + r) * Kd + c0 + c4);
            float* d = &As[r * 36 + c4];
            d[0] = v.x; d[1] = v.y; d[2] = v.z; d[3] = v.w;
        }
        // W tile: 64x32 (512 float4)
#pragma unroll
        for (int i = 0; i < 2; i++) {
            int idx = tid + i * 256;
            int r = idx >> 3, c4 = (idx & 7) * 4;
            float4 v = *(const float4*)(W + (size_t)(bn + r) * Kd + c0 + c4);
            float* d = &Ws[r * 36 + c4];
            d[0] = v.x; d[1] = v.y; d[2] = v.z; d[3] = v.w;
        }
        __syncthreads();

#pragma unroll
        for (int kc = 0; kc < 4; kc++) {
            unsigned ah[2][4], al[2][4];
#pragma unroll
            for (int mt = 0; mt < 2; mt++) {
                int row = wm * 32 + mt * 16 + grp;
                int col = kc * 8 + tig;
                tf32_split(As[row * 36 + col],           ah[mt][0], al[mt][0]);
                tf32_split(As[(row + 8) * 36 + col],     ah[mt][1], al[mt][1]);
                tf32_split(As[row * 36 + col + 4],       ah[mt][2], al[mt][2]);
                tf32_split(As[(row + 8) * 36 + col + 4], ah[mt][3], al[mt][3]);
            }
#pragma unroll
            for (int nt = 0; nt < 4; nt++) {
                int n = wn * 32 + nt * 8 + grp;
                int col = kc * 8 + tig;
                unsigned bh0, bl0, bh1, bl1;
                tf32_split(Ws[n * 36 + col],     bh0, bl0);
                tf32_split(Ws[n * 36 + col + 4], bh1, bl1);
#pragma unroll
                for (int mt = 0; mt < 2; mt++) {
                    mma_tf32(acc[mt][nt], ah[mt][0], ah[mt][1], ah[mt][2], ah[mt][3], bh0, bh1);
                    mma_tf32(acc[mt][nt], ah[mt][0], ah[mt][1], ah[mt][2], ah[mt][3], bl0, bl1);
                    mma_tf32(acc[mt][nt], al[mt][0], al[mt][1], al[mt][2], al[mt][3], bh0, bh1);
                }
            }
        }
        __syncthreads();
    }

#pragma unroll
    for (int mt = 0; mt < 2; mt++) {
#pragma unroll
        for (int nt = 0; nt < 4; nt++) {
            int row = bm + wm * 32 + mt * 16 + grp;
            int col = bn + wn * 32 + nt * 8 + tig * 2;
            float2 bv = *(const float2*)(bias + col);
            float2 v0 = { acc[mt][nt][0] + bv.x, acc[mt][nt][1] + bv.y };
            float2 v1 = { acc[mt][nt][2] + bv.x, acc[mt][nt][3] + bv.y };
            *(float2*)(Cout + (size_t)row * Nn + col)       = v0;
            *(float2*)(Cout + (size_t)(row + 8) * Nn + col) = v1;
        }
    }
}

// ---------------- kernel 5: flash attention, tf32-split MMA ----------------
// grid (KK/64, NH, BB), 128 threads (4 warps, 16 query rows each).
// KV tile = 64 keys per iteration. STATIC smem (<48KB): Ks/Vs 64x36, Ps 64x68.
__global__ void attn_tf32_kernel(const float* __restrict__ Q,
                                 const float* __restrict__ Kb,
                                 const float* __restrict__ Vb,
                                 float* __restrict__ O)
{
    __shared__ float Ks[64 * 36];
    __shared__ float Vs[64 * 36];
    __shared__ float Ps[64 * 68];

    int tid  = threadIdx.x;   // 128
    int lane = tid & 31;
    int warp = tid >> 5;      // 0..3
    int grp = lane >> 2;      // 0..7
    int tig = lane & 3;       // 0..3
    int wr = warp * 16;

    int m0 = blockIdx.x * 64;
    int hh = blockIdx.y;
    int b  = blockIdx.z;
    size_t base = (size_t)b * KK * CC + hh * HD;
    const float scale = 0.17677669529663687f;  // 1/sqrt(32)

    // stage Q tile (pre-scaled) into Ps area, then build per-warp Q fragments
#pragma unroll
    for (int i = 0; i < 4; i++) {
        int idx = tid + i * 128;              // 512 float4 = 64 rows x 8 float4
        int r = idx >> 3, c4 = (idx & 7) * 4;
        float4 v = *(const float4*)(Q + base + (size_t)(m0 + r) * CC + c4);
        float* d = &Ps[r * 36 + c4];
        d[0] = v.x * scale; d[1] = v.y * scale; d[2] = v.z * scale; d[3] = v.w * scale;
    }
    __syncthreads();

    unsigned qh[4][4], ql[4][4];
#pragma unroll
    for (int kc = 0; kc < 4; kc++) {
        int row = wr + grp;
        int col = kc * 8 + tig;
        tf32_split(Ps[row * 36 + col],           qh[kc][0], ql[kc][0]);
        tf32_split(Ps[(row + 8) * 36 + col],     qh[kc][1], ql[kc][1]);
        tf32_split(Ps[row * 36 + col + 4],       qh[kc][2], ql[kc][2]);
        tf32_split(Ps[(row + 8) * 36 + col + 4], qh[kc][3], ql[kc][3]);
    }
    __syncthreads();

    float mr0 = -INFINITY, mr1 = -INFINITY, l0 = 0.f, l1 = 0.f;
    float oacc[4][4];
#pragma unroll
    for (int dt = 0; dt < 4; dt++)
#pragma unroll
        for (int j = 0; j < 4; j++) oacc[dt][j] = 0.f;

    for (int n0 = 0; n0 < KK; n0 += 64) {
        __syncthreads();
#pragma unroll
        for (int i = 0; i < 4; i++) {       // K tile 64x32 (512 float4)
            int idx = tid + i * 128;
            int r = idx >> 3, c4 = (idx & 7) * 4;
            float4 v = *(const float4*)(Kb + base + (size_t)(n0 + r) * CC + c4);
            float* d = &Ks[r * 36 + c4];
            d[0] = v.x; d[1] = v.y; d[2] = v.z; d[3] = v.w;
        }
#pragma unroll
        for (int i = 0; i < 4; i++) {       // V tile 64x32
            int idx = tid + i * 128;
            int r = idx >> 3, c4 = (idx & 7) * 4;
            float4 v = *(const float4*)(Vb + base + (size_t)(n0 + r) * CC + c4);
            float* d = &Vs[r * 36 + c4];
            d[0] = v.x; d[1] = v.y; d[2] = v.z; d[3] = v.w;
        }
        __syncthreads();

        // S = Q K^T  (16 rows x 64 keys per warp)
        float s[8][4];
#pragma unroll
        for (int nt = 0; nt < 8; nt++) {
            s[nt][0] = s[nt][1] = s[nt][2] = s[nt][3] = 0.f;
        }
#pragma unroll
        for (int kc = 0; kc < 4; kc++) {
#pragma unroll
            for (int nt = 0; nt < 8; nt++) {
                int n = nt * 8 + grp;
                int col = kc * 8 + tig;
                unsigned bh0, bl0, bh1, bl1;
                tf32_split(Ks[n * 36 + col],     bh0, bl0);
                tf32_split(Ks[n * 36 + col + 4], bh1, bl1);
                mma_tf32(s[nt], qh[kc][0], qh[kc][1], qh[kc][2], qh[kc][3], bh0, bh1);
                mma_tf32(s[nt], qh[kc][0], qh[kc][1], qh[kc][2], qh[kc][3], bl0, bl1);
                mma_tf32(s[nt], ql[kc][0], ql[kc][1], ql[kc][2], ql[kc][3], bh0, bh1);
            }
        }

        // online softmax (rows wr+grp and wr+grp+8)
        float tm0 = -INFINITY, tm1 = -INFINITY;
#pragma unroll
        for (int nt = 0; nt < 8; nt++) {
            tm0 = fmaxf(tm0, fmaxf(s[nt][0], s[nt][1]));
            tm1 = fmaxf(tm1, fmaxf(s[nt][2], s[nt][3]));
        }
        tm0 = fmaxf(tm0, __shfl_xor_sync(0xffffffff, tm0, 1));
        tm0 = fmaxf(tm0, __shfl_xor_sync(0xffffffff, tm0, 2));
        tm1 = fmaxf(tm1, __shfl_xor_sync(0xffffffff, tm1, 1));
        tm1 = fmaxf(tm1, __shfl_xor_sync(0xffffffff, tm1, 2));

        float mn0 = fmaxf(mr0, tm0), mn1 = fmaxf(mr1, tm1);
        float corr0 = __expf(mr0 - mn0), corr1 = __expf(mr1 - mn1);
        float ps0 = 0.f, ps1 = 0.f;
#pragma unroll
        for (int nt = 0; nt < 8; nt++) {
            float p0 = __expf(s[nt][0] - mn0);
            float p1 = __expf(s[nt][1] - mn0);
            float p2 = __expf(s[nt][2] - mn1);
            float p3 = __expf(s[nt][3] - mn1);
            ps0 += p0 + p1; ps1 += p2 + p3;
            int row = wr + grp;
            int col = nt * 8 + tig * 2;
            *(float2*)&Ps[row * 68 + col]       = make_float2(p0, p1);
            *(float2*)&Ps[(row + 8) * 68 + col] = make_float2(p2, p3);
        }
        ps0 += __shfl_xor_sync(0xffffffff, ps0, 1);
        ps0 += __shfl_xor_sync(0xffffffff, ps0, 2);
        ps1 += __shfl_xor_sync(0xffffffff, ps1, 1);
        ps1 += __shfl_xor_sync(0xffffffff, ps1, 2);
        l0 = l0 * corr0 + ps0;
        l1 = l1 * corr1 + ps1;
#pragma unroll
        for (int dt = 0; dt < 4; dt++) {
            oacc[dt][0] *= corr0; oacc[dt][1] *= corr0;
            oacc[dt][2] *= corr1; oacc[dt][3] *= corr1;
        }
        mr0 = mn0; mr1 = mn1;
        __syncwarp();

        // O += P V  (P rows are per-warp private in Ps)
#pragma unroll
        for (int kc = 0; kc < 8; kc++) {
            int row = wr + grp;
            int col = kc * 8 + tig;
            unsigned ph0, pl0, ph1, pl1, ph2, pl2, ph3, pl3;
            tf32_split(Ps[row * 68 + col],           ph0, pl0);
            tf32_split(Ps[(row + 8) * 68 + col],     ph1, pl1);
            tf32_split(Ps[row * 68 + col + 4],       ph2, pl2);
            tf32_split(Ps[(row + 8) * 68 + col + 4], ph3, pl3);
#pragma unroll
            for (int dt = 0; dt < 4; dt++) {
                unsigned bh0, bl0, bh1, bl1;
                tf32_split(Vs[(kc * 8 + tig) * 36 + dt * 8 + grp],     bh0, bl0);
                tf32_split(Vs[(kc * 8 + tig + 4) * 36 + dt * 8 + grp], bh1, bl1);
                mma_tf32(oacc[dt], ph0, ph1, ph2, ph3, bh0, bh1);
                mma_tf32(oacc[dt], ph0, ph1, ph2, ph3, bl0, bl1);
                mma_tf32(oacc[dt], pl0, pl1, pl2, pl3, bh0, bh1);
            }
        }
        __syncwarp();
    }

    float inv0 = 1.0f / l0, inv1 = 1.0f / l1;
    int row = m0 + wr + grp;
#pragma unroll
    for (int dt = 0; dt < 4; dt++) {
        int col = dt * 8 + tig * 2;
        float2 v0 = { oacc[dt][0] * inv0, oacc[dt][1] * inv0 };
        float2 v1 = { oacc[dt][2] * inv1, oacc[dt][3] * inv1 };
        *(float2*)(O + base + (size_t)row * CC + col)       = v0;
        *(float2*)(O + base + (size_t)(row + 8) * CC + col) = v1;
    }
}

// ---------------- kernel 6: residual + LayerNorm ----------------
__global__ void ln_kernel(const float* __restrict__ P,
                          const float* __restrict__ X,
                          const float* __restrict__ g,
                          const float* __restrict__ beta,
                          float* __restrict__ E)
{
    int row = blockIdx.x;
    int c = threadIdx.x;
    size_t off = (size_t)row * CC + c;
    float y = P[off] + X[off];
    float v1 = y, v2 = y * y;
#pragma unroll
    for (int o = 16; o > 0; o >>= 1) {
        v1 += __shfl_xor_sync(0xffffffff, v1, o);
        v2 += __shfl_xor_sync(0xffffffff, v2, o);
    }
    __shared__ float s1[8], s2[8];
    int w = c >> 5, ln = c & 31;
    if (ln == 0) { s1[w] = v1; s2[w] = v2; }
    __syncthreads();
    float sum = 0.f, sq = 0.f;
#pragma unroll
    for (int i = 0; i < 8; i++) { sum += s1[i]; sq += s2[i]; }
    float mu  = sum * (1.0f / CC);
    float var = sq * (1.0f / CC) - mu * mu;
    float rs  = rsqrtf(var + 1e-5f);
    E[off] = (y - mu) * rs * g[c] + beta[c];
}

// ---------------- kernel 7: copy x -> out, overlay enhanced tokens ----------------
__global__ void scatter_kernel(const float* __restrict__ X,
                               const int* __restrict__ pos2k,
                               const float* __restrict__ E,
                               float* __restrict__ out)
{
    int gid = blockIdx.x * 256 + threadIdx.x;
    int b = gid >> 20;
    int c = (gid >> 12) & (CC - 1);
    int p = gid & (NN - 1);
    int k = pos2k[(b << 12) + p];
    float v = (k >= 0) ? E[(size_t)(((b << 10) + k) << 8) + c] : X[gid];
    out[gid] = v;
}

// ---------------- launch ----------------
extern "C" void kernel_launch(void* const* d_in, const int* in_sizes, int n_in,
                              void* d_out, int out_size)
{
    const float* x    = (const float*)d_in[0];
    const float* bmap = (const float*)d_in[1];
    const float* iw1  = (const float*)d_in[2];
    const float* ib1  = (const float*)d_in[3];
    const float* iw2  = (const float*)d_in[4];
    const float* ib2  = (const float*)d_in[5];
    const float* wq   = (const float*)d_in[6];
    const float* bq   = (const float*)d_in[7];
    const float* wk   = (const float*)d_in[8];
    const float* bk   = (const float*)d_in[9];
    const float* wv   = (const float*)d_in[10];
    const float* bv   = (const float*)d_in[11];
    const float* wo   = (const float*)d_in[12];
    const float* bo   = (const float*)d_in[13];
    const float* lng  = (const float*)d_in[14];
    const float* lnb  = (const float*)d_in[15];

    static float *P_imp = nullptr, *P_xsp, *P_q, *P_k, *P_v, *P_ao, *P_ps, *P_enh;
    static int *P_topidx, *P_pos2k;
    if (!P_imp) {
        cudaGetSymbolAddress((void**)&P_imp,    g_imp);
        cudaGetSymbolAddress((void**)&P_topidx, g_topidx);
        cudaGetSymbolAddress((void**)&P_pos2k,  g_pos2k);
        cudaGetSymbolAddress((void**)&P_xsp,    g_xsp);
        cudaGetSymbolAddress((void**)&P_q,      g_q);
        cudaGetSymbolAddress((void**)&P_k,      g_k);
        cudaGetSymbolAddress((void**)&P_v,      g_v);
        cudaGetSymbolAddress((void**)&P_ao,     g_ao);
        cudaGetSymbolAddress((void**)&P_ps,     g_ps);
        cudaGetSymbolAddress((void**)&P_enh,    g_enh);
    }

    float* out = (float*)d_out;
    float* imp_out = (out_size >= BB * CC * NN + BB * NN) ? out + (size_t)BB * CC * NN
                                                          : nullptr;

    importance_kernel<<<BB * (NN / 256), 256>>>(x, bmap, iw1, ib1, iw2, ib2,
                                                P_imp, imp_out);
    topk_kernel<<<BB, 1024>>>(P_imp, P_topidx, P_pos2k);
    gather_kernel<<<(BB * KK * CC) / 256, 256>>>(x, P_topidx, P_xsp);

    // fused QKV projections (grid.z selects weight set)
    dim3 ggrid3(CC / 64, (BB * KK) / 128, 3);
    gemm_tf32_kernel<<<ggrid3, 256>>>(P_xsp,
                                      wq, bq, P_q,
                                      wk, bk, P_k,
                                      wv, bv, P_v,
                                      BB * KK, CC, CC);

    dim3 agrid(KK / 64, NH, BB);
    attn_tf32_kernel<<<agrid, 128>>>(P_q, P_k, P_v, P_ao);

    dim3 ggrid1(CC / 64, (BB * KK) / 128, 1);
    gemm_tf32_kernel<<<ggrid1, 256>>>(P_ao,
                                      wo, bo, P_ps,
                                      wo, bo, P_ps,
                                      wo, bo, P_ps,
                                      BB * KK, CC, CC);

    ln_kernel<<<BB * KK, 256>>>(P_ps, P_xsp, lng, lnb, P_enh);
    scatter_kernel<<<(BB * CC * NN) / 256, 256>>>(x, P_pos2k, P_enh, out);
}

// round 6
// speedup vs baseline: 1.8561x; 1.1966x over previous
#include <cuda_runtime.h>
#include <math.h>

// Problem constants
#define BB   8
#define CC   256
#define NN   4096          // H*W
#define KK   1024          // top-K
#define NH   8
#define HD   32
#define CH   64            // importance hidden

// ---------------- scratch (device globals; no allocation) ----------------
__device__ float g_imp  [BB * NN];
__device__ int   g_topidx[BB * KK];
__device__ int   g_pos2k [BB * NN];
__device__ float g_xsp  [BB * KK * CC];
__device__ float g_q    [BB * KK * CC];
__device__ float g_k    [BB * KK * CC];
__device__ float g_v    [BB * KK * CC];
__device__ float g_ao   [BB * KK * CC];
__device__ float g_ps   [BB * KK * CC];
__device__ float g_enh  [BB * KK * CC];

// ---------------- tf32 mma helpers ----------------
__device__ __forceinline__ void mma_tf32(float* d,
                                         unsigned a0, unsigned a1, unsigned a2, unsigned a3,
                                         unsigned b0, unsigned b1)
{
    asm volatile(
        "mma.sync.aligned.m16n8k8.row.col.f32.tf32.tf32.f32 "
        "{%0,%1,%2,%3}, {%4,%5,%6,%7}, {%8,%9}, {%0,%1,%2,%3};\n"
        : "+f"(d[0]), "+f"(d[1]), "+f"(d[2]), "+f"(d[3])
        : "r"(a0), "r"(a1), "r"(a2), "r"(a3), "r"(b0), "r"(b1));
}

// exact split: x = hi + lo, both exactly representable in tf32
__device__ __forceinline__ void tf32_split(float x, unsigned& hi, unsigned& lo)
{
    unsigned h = __float_as_uint(x) & 0xFFFFE000u;
    hi = h;
    lo = __float_as_uint(x - __uint_as_float(h));
}

__device__ __forceinline__ unsigned tf32_hi(float x)
{
    return __float_as_uint(x) & 0xFFFFE000u;
}

// ---------------- kernel 1: importance net (tf32-split MMA, fused) ----------------
// h = gelu(x^T W1^T + b1); imp = sigmoid(h w2 + b2) + 0.5*boundary
// per block: 128 pixels x 64 hidden, K=256 channels. grid: 32 p-tiles x 8 batches.
__global__ void importance_mma_kernel(const float* __restrict__ x,
                                      const float* __restrict__ bmap,
                                      const float* __restrict__ w1,
                                      const float* __restrict__ b1,
                                      const float* __restrict__ w2,
                                      const float* __restrict__ b2,
                                      float* __restrict__ imp,
                                      float* __restrict__ imp_out)
{
    __shared__ union {
        struct { float As[32 * 132]; float Ws[64 * 36]; } t;   // GEMM tiles
        float Hs[128 * 65];                                     // gelu(h) overlay
    } u;
    __shared__ float b1s[64], w2s[64];

    int tid  = threadIdx.x;   // 256
    int lane = tid & 31;
    int warp = tid >> 5;
    int wm = warp >> 1;
    int wn = warp & 1;
    int grp = lane >> 2;
    int tig = lane & 3;

    int b  = blockIdx.x >> 5;
    int p0 = (blockIdx.x & 31) * 128;

    if (tid < 64) { b1s[tid] = b1[tid]; w2s[tid] = w2[tid]; }

    float acc[2][4][4];
#pragma unroll
    for (int mt = 0; mt < 2; mt++)
#pragma unroll
        for (int nt = 0; nt < 4; nt++)
#pragma unroll
            for (int j = 0; j < 4; j++) acc[mt][nt][j] = 0.f;

    for (int c0 = 0; c0 < CC; c0 += 32) {
        __syncthreads();   // also protects b1s/w2s on first pass, Hs overlay later
        // A tile: 32 channels x 128 pixels, coalesced along p
#pragma unroll
        for (int i = 0; i < 4; i++) {
            int idx = tid + i * 256;               // 1024 float4 slots
            int cl = idx >> 5, p4 = (idx & 31) * 4;
            float4 v = *(const float4*)(x + (((size_t)(b * CC + c0 + cl)) << 12) + p0 + p4);
            float* d = &u.t.As[cl * 132 + p4];
            d[0] = v.x; d[1] = v.y; d[2] = v.z; d[3] = v.w;
        }
        // W tile: 64 j x 32 channels
#pragma unroll
        for (int i = 0; i < 2; i++) {
            int idx = tid + i * 256;               // 512 float4 slots
            int j = idx >> 3, c4 = (idx & 7) * 4;
            float4 v = *(const float4*)(w1 + j * CC + c0 + c4);
            float* d = &u.t.Ws[j * 36 + c4];
            d[0] = v.x; d[1] = v.y; d[2] = v.z; d[3] = v.w;
        }
        __syncthreads();

#pragma unroll
        for (int kc = 0; kc < 4; kc++) {
            unsigned ah[2][4], al[2][4];
#pragma unroll
            for (int mt = 0; mt < 2; mt++) {
                int row = wm * 32 + mt * 16 + grp;
                int col = kc * 8 + tig;
                tf32_split(u.t.As[col * 132 + row],           ah[mt][0], al[mt][0]);
                tf32_split(u.t.As[col * 132 + row + 8],       ah[mt][1], al[mt][1]);
                tf32_split(u.t.As[(col + 4) * 132 + row],     ah[mt][2], al[mt][2]);
                tf32_split(u.t.As[(col + 4) * 132 + row + 8], ah[mt][3], al[mt][3]);
            }
#pragma unroll
            for (int nt = 0; nt < 4; nt++) {
                int n = wn * 32 + nt * 8 + grp;
                int col = kc * 8 + tig;
                unsigned bh0, bl0, bh1, bl1;
                tf32_split(u.t.Ws[n * 36 + col],     bh0, bl0);
                tf32_split(u.t.Ws[n * 36 + col + 4], bh1, bl1);
#pragma unroll
                for (int mt = 0; mt < 2; mt++) {
                    mma_tf32(acc[mt][nt], ah[mt][0], ah[mt][1], ah[mt][2], ah[mt][3], bh0, bh1);
                    mma_tf32(acc[mt][nt], ah[mt][0], ah[mt][1], ah[mt][2], ah[mt][3], bl0, bl1);
                    mma_tf32(acc[mt][nt], al[mt][0], al[mt][1], al[mt][2], al[mt][3], bh0, bh1);
                }
            }
        }
    }
    __syncthreads();   // done reading As/Ws; safe to overlay Hs

    // epilogue: bias + exact GELU into smem
#pragma unroll
    for (int mt = 0; mt < 2; mt++) {
#pragma unroll
        for (int nt = 0; nt < 4; nt++) {
#pragma unroll
            for (int j = 0; j < 4; j++) {
                int row = wm * 32 + mt * 16 + grp + ((j >= 2) ? 8 : 0);
                int col = wn * 32 + nt * 8 + tig * 2 + (j & 1);
                float v = acc[mt][nt][j] + b1s[col];
                u.Hs[row * 65 + col] = 0.5f * v * (1.0f + erff(v * 0.70710678118654752f));
            }
        }
    }
    __syncthreads();

    // reduce 64 hidden per row (2 threads per row), sigmoid + boundary
    int row = tid >> 1;
    int jh  = (tid & 1) * 32;
    float s = 0.f;
#pragma unroll
    for (int jj = 0; jj < 32; jj++) s += u.Hs[row * 65 + jh + jj] * w2s[jh + jj];
    s += __shfl_xor_sync(0xffffffff, s, 1);
    if ((tid & 1) == 0) {
        float acc2 = s + b2[0];
        float sg  = 1.0f / (1.0f + __expf(-acc2));
        float val = sg + 0.5f * bmap[(b << 12) + p0 + row];
        imp[(b << 12) + p0 + row] = val;
        if (imp_out) imp_out[(b << 12) + p0 + row] = val;
    }
}

// ---------------- kernel 2: exact top-K via bitonic sort ----------------
__global__ void topk_kernel(const float* __restrict__ imp,
                            int* __restrict__ topidx,
                            int* __restrict__ pos2k)
{
    __shared__ unsigned long long keys[NN];
    __shared__ int idxs[KK];
    int tid = threadIdx.x;  // 1024
    int b = blockIdx.x;

    for (int i = tid; i < NN; i += 1024) {
        unsigned int fb = __float_as_uint(imp[(b << 12) + i]);
        keys[i] = ((unsigned long long)fb << 32) | (unsigned int)(NN - 1 - i);
        pos2k[(b << 12) + i] = -1;
    }
    __syncthreads();

    for (int k2 = 2; k2 <= NN; k2 <<= 1) {
        for (int j = k2 >> 1; j > 0; j >>= 1) {
            for (int t = tid; t < NN; t += 1024) {
                int ixj = t ^ j;
                if (ixj > t) {
                    unsigned long long a = keys[t], c = keys[ixj];
                    if ((a < c) == ((t & k2) == 0)) { keys[t] = c; keys[ixj] = a; }
                }
            }
            __syncthreads();
        }
    }
    idxs[tid] = (NN - 1) - (int)(keys[tid] & 0xFFFFFFFFull);
    __syncthreads();
    for (int k2 = 2; k2 <= KK; k2 <<= 1) {
        for (int j = k2 >> 1; j > 0; j >>= 1) {
            int ixj = tid ^ j;
            if (ixj > tid) {
                int a = idxs[tid], c = idxs[ixj];
                if ((a > c) == ((tid & k2) == 0)) { idxs[tid] = c; idxs[ixj] = a; }
            }
            __syncthreads();
        }
    }
    int p = idxs[tid];
    topidx[(b << 10) + tid] = p;
    pos2k[(b << 12) + p] = tid;
}

// ---------------- kernel 3: gather via smem transpose ----------------
// grid (32 k-tiles, 8 c-tiles, 8 b); 256 threads; tile = 32k x 32c.
__global__ void gather_kernel(const float* __restrict__ x,
                              const int* __restrict__ topidx,
                              float* __restrict__ xsp)
{
    __shared__ float sm[32][33];
    int k0 = blockIdx.x * 32;
    int c0 = blockIdx.y * 32;
    int b  = blockIdx.z;
    int tid = threadIdx.x;
    int l = tid & 31, g = tid >> 5;   // 8 groups

    int p = topidx[(b << 10) + k0 + l];
#pragma unroll
    for (int r = 0; r < 4; r++) {
        int cl = g + r * 8;
        sm[cl][l] = x[(((size_t)(b * CC + c0 + cl)) << 12) + p];
    }
    __syncthreads();
#pragma unroll
    for (int r = 0; r < 4; r++) {
        int kl = g + r * 8;
        xsp[(((size_t)((b << 10) + k0 + kl)) << 8) + c0 + l] = sm[l][kl];
    }
}

// ---------------- kernel 4: tf32-split GEMM with register-prefetch ----------------
// block tile 128x64, 256 threads, K-chunk 32; next chunk's gmem loads overlap compute.
__global__ void gemm_tf32_kernel(const float* __restrict__ A,
                                 const float* __restrict__ W0, const float* __restrict__ B0, float* __restrict__ C0,
                                 const float* __restrict__ W1, const float* __restrict__ B1, float* __restrict__ C1,
                                 const float* __restrict__ W2, const float* __restrict__ B2, float* __restrict__ C2,
                                 int M, int Nn, int Kd)
{
    const float* W    = W0;
    const float* bias = B0;
    float*       Cout = C0;
    if (blockIdx.z == 1)      { W = W1; bias = B1; Cout = C1; }
    else if (blockIdx.z == 2) { W = W2; bias = B2; Cout = C2; }

    __shared__ float As[128 * 36];
    __shared__ float Ws[64 * 36];

    int tid  = threadIdx.x;
    int lane = tid & 31;
    int warp = tid >> 5;
    int wm = warp >> 1;
    int wn = warp & 1;
    int grp = lane >> 2;
    int tig = lane & 3;

    int bm = blockIdx.y * 128;
    int bn = blockIdx.x * 64;

    float acc[2][4][4];
#pragma unroll
    for (int mt = 0; mt < 2; mt++)
#pragma unroll
        for (int nt = 0; nt < 4; nt++)
#pragma unroll
            for (int j = 0; j < 4; j++) acc[mt][nt][j] = 0.f;

    float4 ra[4], rw[2];
    // prologue: chunk 0 into registers
#pragma unroll
    for (int i = 0; i < 4; i++) {
        int idx = tid + i * 256;
        int r = idx >> 3, c4 = (idx & 7) * 4;
        ra[i] = *(const float4*)(A + (size_t)(bm + r) * Kd + c4);
    }
#pragma unroll
    for (int i = 0; i < 2; i++) {
        int idx = tid + i * 256;
        int r = idx >> 3, c4 = (idx & 7) * 4;
        rw[i] = *(const float4*)(W + (size_t)(bn + r) * Kd + c4);
    }

    for (int c0 = 0; c0 < Kd; c0 += 32) {
        // commit current chunk to smem
#pragma unroll
        for (int i = 0; i < 4; i++) {
            int idx = tid + i * 256;
            int r = idx >> 3, c4 = (idx & 7) * 4;
            float* d = &As[r * 36 + c4];
            d[0] = ra[i].x; d[1] = ra[i].y; d[2] = ra[i].z; d[3] = ra[i].w;
        }
#pragma unroll
        for (int i = 0; i < 2; i++) {
            int idx = tid + i * 256;
            int r = idx >> 3, c4 = (idx & 7) * 4;
            float* d = &Ws[r * 36 + c4];
            d[0] = rw[i].x; d[1] = rw[i].y; d[2] = rw[i].z; d[3] = rw[i].w;
        }
        __syncthreads();

        // prefetch next chunk (overlaps MMA below)
        if (c0 + 32 < Kd) {
#pragma unroll
            for (int i = 0; i < 4; i++) {
                int idx = tid + i * 256;
                int r = idx >> 3, c4 = (idx & 7) * 4;
                ra[i] = *(const float4*)(A + (size_t)(bm + r) * Kd + c0 + 32 + c4);
            }
#pragma unroll
            for (int i = 0; i < 2; i++) {
                int idx = tid + i * 256;
                int r = idx >> 3, c4 = (idx & 7) * 4;
                rw[i] = *(const float4*)(W + (size_t)(bn + r) * Kd + c0 + 32 + c4);
            }
        }

#pragma unroll
        for (int kc = 0; kc < 4; kc++) {
            unsigned ah[2][4], al[2][4];
#pragma unroll
            for (int mt = 0; mt < 2; mt++) {
                int row = wm * 32 + mt * 16 + grp;
                int col = kc * 8 + tig;
                tf32_split(As[row * 36 + col],           ah[mt][0], al[mt][0]);
                tf32_split(As[(row + 8) * 36 + col],     ah[mt][1], al[mt][1]);
                tf32_split(As[row * 36 + col + 4],       ah[mt][2], al[mt][2]);
                tf32_split(As[(row + 8) * 36 + col + 4], ah[mt][3], al[mt][3]);
            }
#pragma unroll
            for (int nt = 0; nt < 4; nt++) {
                int n = wn * 32 + nt * 8 + grp;
                int col = kc * 8 + tig;
                unsigned bh0, bl0, bh1, bl1;
                tf32_split(Ws[n * 36 + col],     bh0, bl0);
                tf32_split(Ws[n * 36 + col + 4], bh1, bl1);
#pragma unroll
                for (int mt = 0; mt < 2; mt++) {
                    mma_tf32(acc[mt][nt], ah[mt][0], ah[mt][1], ah[mt][2], ah[mt][3], bh0, bh1);
                    mma_tf32(acc[mt][nt], ah[mt][0], ah[mt][1], ah[mt][2], ah[mt][3], bl0, bl1);
                    mma_tf32(acc[mt][nt], al[mt][0], al[mt][1], al[mt][2], al[mt][3], bh0, bh1);
                }
            }
        }
        __syncthreads();
    }

#pragma unroll
    for (int mt = 0; mt < 2; mt++) {
#pragma unroll
        for (int nt = 0; nt < 4; nt++) {
            int row = bm + wm * 32 + mt * 16 + grp;
            int col = bn + wn * 32 + nt * 8 + tig * 2;
            float2 bv = *(const float2*)(bias + col);
            float2 v0 = { acc[mt][nt][0] + bv.x, acc[mt][nt][1] + bv.y };
            float2 v1 = { acc[mt][nt][2] + bv.x, acc[mt][nt][3] + bv.y };
            *(float2*)(Cout + (size_t)row * Nn + col)       = v0;
            *(float2*)(Cout + (size_t)(row + 8) * Nn + col) = v1;
        }
    }
}

// ---------------- kernel 5: flash attention, tf32-split MMA ----------------
// grid (KK/64, NH, BB), 128 threads (4 warps, 16 query rows each).
// QK: 3-term split (exact). PV: P truncated to tf32, V split exact (2 MMAs).
__global__ void attn_tf32_kernel(const float* __restrict__ Q,
                                 const float* __restrict__ Kb,
                                 const float* __restrict__ Vb,
                                 float* __restrict__ O)
{
    __shared__ float Ks[64 * 36];
    __shared__ float Vs[64 * 36];
    __shared__ float Ps[64 * 68];

    int tid  = threadIdx.x;   // 128
    int lane = tid & 31;
    int warp = tid >> 5;      // 0..3
    int grp = lane >> 2;      // 0..7
    int tig = lane & 3;       // 0..3
    int wr = warp * 16;

    int m0 = blockIdx.x * 64;
    int hh = blockIdx.y;
    int b  = blockIdx.z;
    size_t base = (size_t)b * KK * CC + hh * HD;
    const float scale = 0.17677669529663687f;  // 1/sqrt(32)

    // stage Q tile (pre-scaled) into Ps area, then build per-warp Q fragments
#pragma unroll
    for (int i = 0; i < 4; i++) {
        int idx = tid + i * 128;              // 512 float4 = 64 rows x 8 float4
        int r = idx >> 3, c4 = (idx & 7) * 4;
        float4 v = *(const float4*)(Q + base + (size_t)(m0 + r) * CC + c4);
        float* d = &Ps[r * 36 + c4];
        d[0] = v.x * scale; d[1] = v.y * scale; d[2] = v.z * scale; d[3] = v.w * scale;
    }
    __syncthreads();

    unsigned qh[4][4], ql[4][4];
#pragma unroll
    for (int kc = 0; kc < 4; kc++) {
        int row = wr + grp;
        int col = kc * 8 + tig;
        tf32_split(Ps[row * 36 + col],           qh[kc][0], ql[kc][0]);
        tf32_split(Ps[(row + 8) * 36 + col],     qh[kc][1], ql[kc][1]);
        tf32_split(Ps[row * 36 + col + 4],       qh[kc][2], ql[kc][2]);
        tf32_split(Ps[(row + 8) * 36 + col + 4], qh[kc][3], ql[kc][3]);
    }
    __syncthreads();

    float mr0 = -INFINITY, mr1 = -INFINITY, l0 = 0.f, l1 = 0.f;
    float oacc[4][4];
#pragma unroll
    for (int dt = 0; dt < 4; dt++)
#pragma unroll
        for (int j = 0; j < 4; j++) oacc[dt][j] = 0.f;

    for (int n0 = 0; n0 < KK; n0 += 64) {
        __syncthreads();
#pragma unroll
        for (int i = 0; i < 4; i++) {       // K tile 64x32 (512 float4)
            int idx = tid + i * 128;
            int r = idx >> 3, c4 = (idx & 7) * 4;
            float4 v = *(const float4*)(Kb + base + (size_t)(n0 + r) * CC + c4);
            float* d = &Ks[r * 36 + c4];
            d[0] = v.x; d[1] = v.y; d[2] = v.z; d[3] = v.w;
        }
#pragma unroll
        for (int i = 0; i < 4; i++) {       // V tile 64x32
            int idx = tid + i * 128;
            int r = idx >> 3, c4 = (idx & 7) * 4;
            float4 v = *(const float4*)(Vb + base + (size_t)(n0 + r) * CC + c4);
            float* d = &Vs[r * 36 + c4];
            d[0] = v.x; d[1] = v.y; d[2] = v.z; d[3] = v.w;
        }
        __syncthreads();

        // S = Q K^T  (16 rows x 64 keys per warp)
        float s[8][4];
#pragma unroll
        for (int nt = 0; nt < 8; nt++) {
            s[nt][0] = s[nt][1] = s[nt][2] = s[nt][3] = 0.f;
        }
#pragma unroll
        for (int kc = 0; kc < 4; kc++) {
#pragma unroll
            for (int nt = 0; nt < 8; nt++) {
                int n = nt * 8 + grp;
                int col = kc * 8 + tig;
                unsigned bh0, bl0, bh1, bl1;
                tf32_split(Ks[n * 36 + col],     bh0, bl0);
                tf32_split(Ks[n * 36 + col + 4], bh1, bl1);
                mma_tf32(s[nt], qh[kc][0], qh[kc][1], qh[kc][2], qh[kc][3], bh0, bh1);
                mma_tf32(s[nt], qh[kc][0], qh[kc][1], qh[kc][2], qh[kc][3], bl0, bl1);
                mma_tf32(s[nt], ql[kc][0], ql[kc][1], ql[kc][2], ql[kc][3], bh0, bh1);
            }
        }

        // online softmax (rows wr+grp and wr+grp+8)
        float tm0 = -INFINITY, tm1 = -INFINITY;
#pragma unroll
        for (int nt = 0; nt < 8; nt++) {
            tm0 = fmaxf(tm0, fmaxf(s[nt][0], s[nt][1]));
            tm1 = fmaxf(tm1, fmaxf(s[nt][2], s[nt][3]));
        }
        tm0 = fmaxf(tm0, __shfl_xor_sync(0xffffffff, tm0, 1));
        tm0 = fmaxf(tm0, __shfl_xor_sync(0xffffffff, tm0, 2));
        tm1 = fmaxf(tm1, __shfl_xor_sync(0xffffffff, tm1, 1));
        tm1 = fmaxf(tm1, __shfl_xor_sync(0xffffffff, tm1, 2));

        float mn0 = fmaxf(mr0, tm0), mn1 = fmaxf(mr1, tm1);
        float corr0 = __expf(mr0 - mn0), corr1 = __expf(mr1 - mn1);
        float ps0 = 0.f, ps1 = 0.f;
#pragma unroll
        for (int nt = 0; nt < 8; nt++) {
            float p0 = __expf(s[nt][0] - mn0);
            float p1 = __expf(s[nt][1] - mn0);
            float p2 = __expf(s[nt][2] - mn1);
            float p3 = __expf(s[nt][3] - mn1);
            ps0 += p0 + p1; ps1 += p2 + p3;
            int row = wr + grp;
            int col = nt * 8 + tig * 2;
            *(float2*)&Ps[row * 68 + col]       = make_float2(p0, p1);
            *(float2*)&Ps[(row + 8) * 68 + col] = make_float2(p2, p3);
        }
        ps0 += __shfl_xor_sync(0xffffffff, ps0, 1);
        ps0 += __shfl_xor_sync(0xffffffff, ps0, 2);
        ps1 += __shfl_xor_sync(0xffffffff, ps1, 1);
        ps1 += __shfl_xor_sync(0xffffffff, ps1, 2);
        l0 = l0 * corr0 + ps0;
        l1 = l1 * corr1 + ps1;
#pragma unroll
        for (int dt = 0; dt < 4; dt++) {
            oacc[dt][0] *= corr0; oacc[dt][1] *= corr0;
            oacc[dt][2] *= corr1; oacc[dt][3] *= corr1;
        }
        mr0 = mn0; mr1 = mn1;
        __syncwarp();

        // O += P V  (P truncated to tf32; V split exact -> 2 MMAs)
#pragma unroll
        for (int kc = 0; kc < 8; kc++) {
            int row = wr + grp;
            int col = kc * 8 + tig;
            unsigned ph0 = tf32_hi(Ps[row * 68 + col]);
            unsigned ph1 = tf32_hi(Ps[(row + 8) * 68 + col]);
            unsigned ph2 = tf32_hi(Ps[row * 68 + col + 4]);
            unsigned ph3 = tf32_hi(Ps[(row + 8) * 68 + col + 4]);
#pragma unroll
            for (int dt = 0; dt < 4; dt++) {
                unsigned bh0, bl0, bh1, bl1;
                tf32_split(Vs[(kc * 8 + tig) * 36 + dt * 8 + grp],     bh0, bl0);
                tf32_split(Vs[(kc * 8 + tig + 4) * 36 + dt * 8 + grp], bh1, bl1);
                mma_tf32(oacc[dt], ph0, ph1, ph2, ph3, bh0, bh1);
                mma_tf32(oacc[dt], ph0, ph1, ph2, ph3, bl0, bl1);
            }
        }
        __syncwarp();
    }

    float inv0 = 1.0f / l0, inv1 = 1.0f / l1;
    int row = m0 + wr + grp;
#pragma unroll
    for (int dt = 0; dt < 4; dt++) {
        int col = dt * 8 + tig * 2;
        float2 v0 = { oacc[dt][0] * inv0, oacc[dt][1] * inv0 };
        float2 v1 = { oacc[dt][2] * inv1, oacc[dt][3] * inv1 };
        *(float2*)(O + base + (size_t)row * CC + col)       = v0;
        *(float2*)(O + base + (size_t)(row + 8) * CC + col) = v1;
    }
}

// ---------------- kernel 6: residual + LayerNorm ----------------
__global__ void ln_kernel(const float* __restrict__ P,
                          const float* __restrict__ X,
                          const float* __restrict__ g,
                          const float* __restrict__ beta,
                          float* __restrict__ E)
{
    int row = blockIdx.x;
    int c = threadIdx.x;
    size_t off = (size_t)row * CC + c;
    float y = P[off] + X[off];
    float v1 = y, v2 = y * y;
#pragma unroll
    for (int o = 16; o > 0; o >>= 1) {
        v1 += __shfl_xor_sync(0xffffffff, v1, o);
        v2 += __shfl_xor_sync(0xffffffff, v2, o);
    }
    __shared__ float s1[8], s2[8];
    int w = c >> 5, ln = c & 31;
    if (ln == 0) { s1[w] = v1; s2[w] = v2; }
    __syncthreads();
    float sum = 0.f, sq = 0.f;
#pragma unroll
    for (int i = 0; i < 8; i++) { sum += s1[i]; sq += s2[i]; }
    float mu  = sum * (1.0f / CC);
    float var = sq * (1.0f / CC) - mu * mu;
    float rs  = rsqrtf(var + 1e-5f);
    E[off] = (y - mu) * rs * g[c] + beta[c];
}

// ---------------- kernel 7: copy x -> out, overlay enhanced tokens ----------------
__global__ void scatter_kernel(const float* __restrict__ X,
                               const int* __restrict__ pos2k,
                               const float* __restrict__ E,
                               float* __restrict__ out)
{
    int gid = blockIdx.x * 256 + threadIdx.x;
    int b = gid >> 20;
    int c = (gid >> 12) & (CC - 1);
    int p = gid & (NN - 1);
    int k = pos2k[(b << 12) + p];
    float v = (k >= 0) ? E[(size_t)(((b << 10) + k) << 8) + c] : X[gid];
    out[gid] = v;
}

// ---------------- launch ----------------
extern "C" void kernel_launch(void* const* d_in, const int* in_sizes, int n_in,
                              void* d_out, int out_size)
{
    const float* x    = (const float*)d_in[0];
    const float* bmap = (const float*)d_in[1];
    const float* iw1  = (const float*)d_in[2];
    const float* ib1  = (const float*)d_in[3];
    const float* iw2  = (const float*)d_in[4];
    const float* ib2  = (const float*)d_in[5];
    const float* wq   = (const float*)d_in[6];
    const float* bq   = (const float*)d_in[7];
    const float* wk   = (const float*)d_in[8];
    const float* bk   = (const float*)d_in[9];
    const float* wv   = (const float*)d_in[10];
    const float* bv   = (const float*)d_in[11];
    const float* wo   = (const float*)d_in[12];
    const float* bo   = (const float*)d_in[13];
    const float* lng  = (const float*)d_in[14];
    const float* lnb  = (const float*)d_in[15];

    static float *P_imp = nullptr, *P_xsp, *P_q, *P_k, *P_v, *P_ao, *P_ps, *P_enh;
    static int *P_topidx, *P_pos2k;
    if (!P_imp) {
        cudaGetSymbolAddress((void**)&P_imp,    g_imp);
        cudaGetSymbolAddress((void**)&P_topidx, g_topidx);
        cudaGetSymbolAddress((void**)&P_pos2k,  g_pos2k);
        cudaGetSymbolAddress((void**)&P_xsp,    g_xsp);
        cudaGetSymbolAddress((void**)&P_q,      g_q);
        cudaGetSymbolAddress((void**)&P_k,      g_k);
        cudaGetSymbolAddress((void**)&P_v,      g_v);
        cudaGetSymbolAddress((void**)&P_ao,     g_ao);
        cudaGetSymbolAddress((void**)&P_ps,     g_ps);
        cudaGetSymbolAddress((void**)&P_enh,    g_enh);
    }

    float* out = (float*)d_out;
    float* imp_out = (out_size >= BB * CC * NN + BB * NN) ? out + (size_t)BB * CC * NN
                                                          : nullptr;

    importance_mma_kernel<<<BB * 32, 256>>>(x, bmap, iw1, ib1, iw2, ib2,
                                            P_imp, imp_out);
    topk_kernel<<<BB, 1024>>>(P_imp, P_topidx, P_pos2k);

    dim3 ggrid_gather(KK / 32, CC / 32, BB);
    gather_kernel<<<ggrid_gather, 256>>>(x, P_topidx, P_xsp);

    // fused QKV projections (grid.z selects weight set)
    dim3 ggrid3(CC / 64, (BB * KK) / 128, 3);
    gemm_tf32_kernel<<<ggrid3, 256>>>(P_xsp,
                                      wq, bq, P_q,
                                      wk, bk, P_k,
                                      wv, bv, P_v,
                                      BB * KK, CC, CC);

    dim3 agrid(KK / 64, NH, BB);
    attn_tf32_kernel<<<agrid, 128>>>(P_q, P_k, P_v, P_ao);

    dim3 ggrid1(CC / 64, (BB * KK) / 128, 1);
    gemm_tf32_kernel<<<ggrid1, 256>>>(P_ao,
                                      wo, bo, P_ps,
                                      wo, bo, P_ps,
                                      wo, bo, P_ps,
                                      BB * KK, CC, CC);

    ln_kernel<<<BB * KK, 256>>>(P_ps, P_xsp, lng, lnb, P_enh);
    scatter_kernel<<<(BB * CC * NN) / 256, 256>>>(x, P_pos2k, P_enh, out);
}

// round 9
// speedup vs baseline: 2.1268x; 1.1458x over previous
#include <cuda_runtime.h>
#include <math.h>

// Problem constants
#define BB   8
#define CC   256
#define NN   4096          // H*W
#define KK   1024          // top-K
#define NH   8
#define HD   32
#define CH   64            // importance hidden

// ---------------- scratch (device globals; no allocation) ----------------
__device__ float g_imp  [BB * NN];
__device__ int   g_topidx[BB * KK];
__device__ int   g_pos2k [BB * NN];
__device__ float g_xsp  [BB * KK * CC];
__device__ float g_q    [BB * KK * CC];
__device__ float g_k    [BB * KK * CC];
__device__ float g_v    [BB * KK * CC];
__device__ float g_ao   [BB * KK * CC];
__device__ float g_ps   [BB * KK * CC];
__device__ float g_enh  [BB * KK * CC];

// ---------------- tf32 mma helpers ----------------
__device__ __forceinline__ void mma_tf32(float* d,
                                         unsigned a0, unsigned a1, unsigned a2, unsigned a3,
                                         unsigned b0, unsigned b1)
{
    asm volatile(
        "mma.sync.aligned.m16n8k8.row.col.f32.tf32.tf32.f32 "
        "{%0,%1,%2,%3}, {%4,%5,%6,%7}, {%8,%9}, {%0,%1,%2,%3};\n"
        : "+f"(d[0]), "+f"(d[1]), "+f"(d[2]), "+f"(d[3])
        : "r"(a0), "r"(a1), "r"(a2), "r"(a3), "r"(b0), "r"(b1));
}

// exact split: x = hi + lo, both exactly representable in tf32
__device__ __forceinline__ void tf32_split(float x, unsigned& hi, unsigned& lo)
{
    unsigned h = __float_as_uint(x) & 0xFFFFE000u;
    hi = h;
    lo = __float_as_uint(x - __uint_as_float(h));
}

__device__ __forceinline__ unsigned tf32_hi(float x)
{
    return __float_as_uint(x) & 0xFFFFE000u;
}

__device__ __forceinline__ float tf32_hi_f(float x)
{
    return __uint_as_float(__float_as_uint(x) & 0xFFFFE000u);
}

// ---------------- kernel 1: importance net (tf32-split MMA, 3-term EXACT) ----------------
// Top-K selection depends on this — keep full fp32-equivalent accuracy.
__global__ void importance_mma_kernel(const float* __restrict__ x,
                                      const float* __restrict__ bmap,
                                      const float* __restrict__ w1,
                                      const float* __restrict__ b1,
                                      const float* __restrict__ w2,
                                      const float* __restrict__ b2,
                                      float* __restrict__ imp,
                                      float* __restrict__ imp_out)
{
    __shared__ union {
        struct { float As[32 * 132]; float Ws[64 * 36]; } t;   // GEMM tiles
        float Hs[128 * 65];                                     // gelu(h) overlay
    } u;
    __shared__ float b1s[64], w2s[64];

    int tid  = threadIdx.x;   // 256
    int lane = tid & 31;
    int warp = tid >> 5;
    int wm = warp >> 1;
    int wn = warp & 1;
    int grp = lane >> 2;
    int tig = lane & 3;

    int b  = blockIdx.x >> 5;
    int p0 = (blockIdx.x & 31) * 128;

    if (tid < 64) { b1s[tid] = b1[tid]; w2s[tid] = w2[tid]; }

    float acc[2][4][4];
#pragma unroll
    for (int mt = 0; mt < 2; mt++)
#pragma unroll
        for (int nt = 0; nt < 4; nt++)
#pragma unroll
            for (int j = 0; j < 4; j++) acc[mt][nt][j] = 0.f;

    for (int c0 = 0; c0 < CC; c0 += 32) {
        __syncthreads();
        // A tile: 32 channels x 128 pixels, coalesced along p
#pragma unroll
        for (int i = 0; i < 4; i++) {
            int idx = tid + i * 256;
            int cl = idx >> 5, p4 = (idx & 31) * 4;
            float4 v = *(const float4*)(x + (((size_t)(b * CC + c0 + cl)) << 12) + p0 + p4);
            float* d = &u.t.As[cl * 132 + p4];
            d[0] = v.x; d[1] = v.y; d[2] = v.z; d[3] = v.w;
        }
        // W tile: 64 j x 32 channels
#pragma unroll
        for (int i = 0; i < 2; i++) {
            int idx = tid + i * 256;
            int j = idx >> 3, c4 = (idx & 7) * 4;
            float4 v = *(const float4*)(w1 + j * CC + c0 + c4);
            float* d = &u.t.Ws[j * 36 + c4];
            d[0] = v.x; d[1] = v.y; d[2] = v.z; d[3] = v.w;
        }
        __syncthreads();

#pragma unroll
        for (int kc = 0; kc < 4; kc++) {
            unsigned ah[2][4], al[2][4];
#pragma unroll
            for (int mt = 0; mt < 2; mt++) {
                int row = wm * 32 + mt * 16 + grp;
                int col = kc * 8 + tig;
                tf32_split(u.t.As[col * 132 + row],           ah[mt][0], al[mt][0]);
                tf32_split(u.t.As[col * 132 + row + 8],       ah[mt][1], al[mt][1]);
                tf32_split(u.t.As[(col + 4) * 132 + row],     ah[mt][2], al[mt][2]);
                tf32_split(u.t.As[(col + 4) * 132 + row + 8], ah[mt][3], al[mt][3]);
            }
#pragma unroll
            for (int nt = 0; nt < 4; nt++) {
                int n = wn * 32 + nt * 8 + grp;
                int col = kc * 8 + tig;
                unsigned bh0, bl0, bh1, bl1;
                tf32_split(u.t.Ws[n * 36 + col],     bh0, bl0);
                tf32_split(u.t.Ws[n * 36 + col + 4], bh1, bl1);
#pragma unroll
                for (int mt = 0; mt < 2; mt++) {
                    mma_tf32(acc[mt][nt], ah[mt][0], ah[mt][1], ah[mt][2], ah[mt][3], bh0, bh1);
                    mma_tf32(acc[mt][nt], ah[mt][0], ah[mt][1], ah[mt][2], ah[mt][3], bl0, bl1);
                    mma_tf32(acc[mt][nt], al[mt][0], al[mt][1], al[mt][2], al[mt][3], bh0, bh1);
                }
            }
        }
    }
    __syncthreads();

    // epilogue: bias + exact GELU into smem
#pragma unroll
    for (int mt = 0; mt < 2; mt++) {
#pragma unroll
        for (int nt = 0; nt < 4; nt++) {
#pragma unroll
            for (int j = 0; j < 4; j++) {
                int row = wm * 32 + mt * 16 + grp + ((j >= 2) ? 8 : 0);
                int col = wn * 32 + nt * 8 + tig * 2 + (j & 1);
                float v = acc[mt][nt][j] + b1s[col];
                u.Hs[row * 65 + col] = 0.5f * v * (1.0f + erff(v * 0.70710678118654752f));
            }
        }
    }
    __syncthreads();

    // reduce 64 hidden per row (2 threads per row), sigmoid + boundary
    int row = tid >> 1;
    int jh  = (tid & 1) * 32;
    float s = 0.f;
#pragma unroll
    for (int jj = 0; jj < 32; jj++) s += u.Hs[row * 65 + jh + jj] * w2s[jh + jj];
    s += __shfl_xor_sync(0xffffffff, s, 1);
    if ((tid & 1) == 0) {
        float acc2 = s + b2[0];
        float sg  = 1.0f / (1.0f + __expf(-acc2));
        float val = sg + 0.5f * bmap[(b << 12) + p0 + row];
        imp[(b << 12) + p0 + row] = val;
        if (imp_out) imp_out[(b << 12) + p0 + row] = val;
    }
}

// ---------------- kernel 2: exact top-K via bitonic sort ----------------
__global__ void topk_kernel(const float* __restrict__ imp,
                            int* __restrict__ topidx,
                            int* __restrict__ pos2k)
{
    __shared__ unsigned long long keys[NN];
    __shared__ int idxs[KK];
    int tid = threadIdx.x;  // 1024
    int b = blockIdx.x;

    for (int i = tid; i < NN; i += 1024) {
        unsigned int fb = __float_as_uint(imp[(b << 12) + i]);
        keys[i] = ((unsigned long long)fb << 32) | (unsigned int)(NN - 1 - i);
        pos2k[(b << 12) + i] = -1;
    }
    __syncthreads();

    for (int k2 = 2; k2 <= NN; k2 <<= 1) {
        for (int j = k2 >> 1; j > 0; j >>= 1) {
            for (int t = tid; t < NN; t += 1024) {
                int ixj = t ^ j;
                if (ixj > t) {
                    unsigned long long a = keys[t], c = keys[ixj];
                    if ((a < c) == ((t & k2) == 0)) { keys[t] = c; keys[ixj] = a; }
                }
            }
            __syncthreads();
        }
    }
    idxs[tid] = (NN - 1) - (int)(keys[tid] & 0xFFFFFFFFull);
    __syncthreads();
    for (int k2 = 2; k2 <= KK; k2 <<= 1) {
        for (int j = k2 >> 1; j > 0; j >>= 1) {
            int ixj = tid ^ j;
            if (ixj > tid) {
                int a = idxs[tid], c = idxs[ixj];
                if ((a > c) == ((tid & k2) == 0)) { idxs[tid] = c; idxs[ixj] = a; }
            }
            __syncthreads();
        }
    }
    int p = idxs[tid];
    topidx[(b << 10) + tid] = p;
    pos2k[(b << 12) + p] = tid;
}

// ---------------- kernel 3: gather via smem transpose ----------------
__global__ void gather_kernel(const float* __restrict__ x,
                              const int* __restrict__ topidx,
                              float* __restrict__ xsp)
{
    __shared__ float sm[32][33];
    int k0 = blockIdx.x * 32;
    int c0 = blockIdx.y * 32;
    int b  = blockIdx.z;
    int tid = threadIdx.x;
    int l = tid & 31, g = tid >> 5;

    int p = topidx[(b << 10) + k0 + l];
#pragma unroll
    for (int r = 0; r < 4; r++) {
        int cl = g + r * 8;
        sm[cl][l] = x[(((size_t)(b * CC + c0 + cl)) << 12) + p];
    }
    __syncthreads();
#pragma unroll
    for (int r = 0; r < 4; r++) {
        int kl = g + r * 8;
        xsp[(((size_t)((b << 10) + k0 + kl)) << 8) + c0 + l] = sm[l][kl];
    }
}

// ---------------- kernel 4: 2-term tf32 GEMM (A truncated AT STORE, W split) ----------------
// acc += ah*bh + ah*bl = ah*b. A tile stored pre-truncated (bit-identical to
// truncating at read; removes one AND per A-fragment element in the hot loop).
__global__ void gemm_tf32_kernel(const float* __restrict__ A,
                                 const float* __restrict__ W0, const float* __restrict__ B0, float* __restrict__ C0,
                                 const float* __restrict__ W1, const float* __restrict__ B1, float* __restrict__ C1,
                                 const float* __restrict__ W2, const float* __restrict__ B2, float* __restrict__ C2,
                                 int M, int Nn, int Kd)
{
    const float* W    = W0;
    const float* bias = B0;
    float*       Cout = C0;
    if (blockIdx.z == 1)      { W = W1; bias = B1; Cout = C1; }
    else if (blockIdx.z == 2) { W = W2; bias = B2; Cout = C2; }

    __shared__ float As[128 * 36];
    __shared__ float Ws[64 * 36];

    int tid  = threadIdx.x;
    int lane = tid & 31;
    int warp = tid >> 5;
    int wm = warp >> 1;
    int wn = warp & 1;
    int grp = lane >> 2;
    int tig = lane & 3;

    int bm = blockIdx.y * 128;
    int bn = blockIdx.x * 64;

    float acc[2][4][4];
#pragma unroll
    for (int mt = 0; mt < 2; mt++)
#pragma unroll
        for (int nt = 0; nt < 4; nt++)
#pragma unroll
            for (int j = 0; j < 4; j++) acc[mt][nt][j] = 0.f;

    float4 ra[4], rw[2];
#pragma unroll
    for (int i = 0; i < 4; i++) {
        int idx = tid + i * 256;
        int r = idx >> 3, c4 = (idx & 7) * 4;
        ra[i] = *(const float4*)(A + (size_t)(bm + r) * Kd + c4);
    }
#pragma unroll
    for (int i = 0; i < 2; i++) {
        int idx = tid + i * 256;
        int r = idx >> 3, c4 = (idx & 7) * 4;
        rw[i] = *(const float4*)(W + (size_t)(bn + r) * Kd + c4);
    }

    for (int c0 = 0; c0 < Kd; c0 += 32) {
        // commit current chunk to smem (A pre-truncated to tf32 bits)
#pragma unroll
        for (int i = 0; i < 4; i++) {
            int idx = tid + i * 256;
            int r = idx >> 3, c4 = (idx & 7) * 4;
            float* d = &As[r * 36 + c4];
            d[0] = tf32_hi_f(ra[i].x); d[1] = tf32_hi_f(ra[i].y);
            d[2] = tf32_hi_f(ra[i].z); d[3] = tf32_hi_f(ra[i].w);
        }
#pragma unroll
        for (int i = 0; i < 2; i++) {
            int idx = tid + i * 256;
            int r = idx >> 3, c4 = (idx & 7) * 4;
            float* d = &Ws[r * 36 + c4];
            d[0] = rw[i].x; d[1] = rw[i].y; d[2] = rw[i].z; d[3] = rw[i].w;
        }
        __syncthreads();

        // prefetch next chunk (overlaps MMA below)
        if (c0 + 32 < Kd) {
#pragma unroll
            for (int i = 0; i < 4; i++) {
                int idx = tid + i * 256;
                int r = idx >> 3, c4 = (idx & 7) * 4;
                ra[i] = *(const float4*)(A + (size_t)(bm + r) * Kd + c0 + 32 + c4);
            }
#pragma unroll
            for (int i = 0; i < 2; i++) {
                int idx = tid + i * 256;
                int r = idx >> 3, c4 = (idx & 7) * 4;
                rw[i] = *(const float4*)(W + (size_t)(bn + r) * Kd + c0 + 32 + c4);
            }
        }

#pragma unroll
        for (int kc = 0; kc < 4; kc++) {
            unsigned ah[2][4];
#pragma unroll
            for (int mt = 0; mt < 2; mt++) {
                int row = wm * 32 + mt * 16 + grp;
                int col = kc * 8 + tig;
                ah[mt][0] = __float_as_uint(As[row * 36 + col]);
                ah[mt][1] = __float_as_uint(As[(row + 8) * 36 + col]);
                ah[mt][2] = __float_as_uint(As[row * 36 + col + 4]);
                ah[mt][3] = __float_as_uint(As[(row + 8) * 36 + col + 4]);
            }
#pragma unroll
            for (int nt = 0; nt < 4; nt++) {
                int n = wn * 32 + nt * 8 + grp;
                int col = kc * 8 + tig;
                unsigned bh0, bl0, bh1, bl1;
                tf32_split(Ws[n * 36 + col],     bh0, bl0);
                tf32_split(Ws[n * 36 + col + 4], bh1, bl1);
#pragma unroll
                for (int mt = 0; mt < 2; mt++) {
                    mma_tf32(acc[mt][nt], ah[mt][0], ah[mt][1], ah[mt][2], ah[mt][3], bh0, bh1);
                    mma_tf32(acc[mt][nt], ah[mt][0], ah[mt][1], ah[mt][2], ah[mt][3], bl0, bl1);
                }
            }
        }
        __syncthreads();
    }

#pragma unroll
    for (int mt = 0; mt < 2; mt++) {
#pragma unroll
        for (int nt = 0; nt < 4; nt++) {
            int row = bm + wm * 32 + mt * 16 + grp;
            int col = bn + wn * 32 + nt * 8 + tig * 2;
            float2 bv = *(const float2*)(bias + col);
            float2 v0 = { acc[mt][nt][0] + bv.x, acc[mt][nt][1] + bv.y };
            float2 v1 = { acc[mt][nt][2] + bv.x, acc[mt][nt][3] + bv.y };
            *(float2*)(Cout + (size_t)row * Nn + col)       = v0;
            *(float2*)(Cout + (size_t)(row + 8) * Nn + col) = v1;
        }
    }
}

// ---------------- kernel 5: flash attention ----------------
// QK: Q split (exact regs) x K truncated-at-store -> 2 MMAs.
// PV: P truncated-at-store x V truncated-at-store -> 1 MMA.
// Bit-identical to the tf32_hi-at-read formulation; ANDs hoisted out of loops.
__global__ void attn_tf32_kernel(const float* __restrict__ Q,
                                 const float* __restrict__ Kb,
                                 const float* __restrict__ Vb,
                                 float* __restrict__ O)
{
    __shared__ float Ks[64 * 36];
    __shared__ float Vs[64 * 36];
    __shared__ float Ps[64 * 68];

    int tid  = threadIdx.x;   // 128
    int lane = tid & 31;
    int warp = tid >> 5;
    int grp = lane >> 2;
    int tig = lane & 3;
    int wr = warp * 16;

    int m0 = blockIdx.x * 64;
    int hh = blockIdx.y;
    int b  = blockIdx.z;
    size_t base = (size_t)b * KK * CC + hh * HD;
    const float scale = 0.17677669529663687f;  // 1/sqrt(32)

    // stage Q tile (pre-scaled, FULL precision) into Ps area; build split fragments
#pragma unroll
    for (int i = 0; i < 4; i++) {
        int idx = tid + i * 128;
        int r = idx >> 3, c4 = (idx & 7) * 4;
        float4 v = *(const float4*)(Q + base + (size_t)(m0 + r) * CC + c4);
        float* d = &Ps[r * 36 + c4];
        d[0] = v.x * scale; d[1] = v.y * scale; d[2] = v.z * scale; d[3] = v.w * scale;
    }
    __syncthreads();

    unsigned qh[4][4], ql[4][4];
#pragma unroll
    for (int kc = 0; kc < 4; kc++) {
        int row = wr + grp;
        int col = kc * 8 + tig;
        tf32_split(Ps[row * 36 + col],           qh[kc][0], ql[kc][0]);
        tf32_split(Ps[(row + 8) * 36 + col],     qh[kc][1], ql[kc][1]);
        tf32_split(Ps[row * 36 + col + 4],       qh[kc][2], ql[kc][2]);
        tf32_split(Ps[(row + 8) * 36 + col + 4], qh[kc][3], ql[kc][3]);
    }
    __syncthreads();

    float mr0 = -INFINITY, mr1 = -INFINITY, l0 = 0.f, l1 = 0.f;
    float oacc[4][4];
#pragma unroll
    for (int dt = 0; dt < 4; dt++)
#pragma unroll
        for (int j = 0; j < 4; j++) oacc[dt][j] = 0.f;

    for (int n0 = 0; n0 < KK; n0 += 64) {
        __syncthreads();
#pragma unroll
        for (int i = 0; i < 4; i++) {       // K tile 64x32, truncated at store
            int idx = tid + i * 128;
            int r = idx >> 3, c4 = (idx & 7) * 4;
            float4 v = *(const float4*)(Kb + base + (size_t)(n0 + r) * CC + c4);
            float* d = &Ks[r * 36 + c4];
            d[0] = tf32_hi_f(v.x); d[1] = tf32_hi_f(v.y);
            d[2] = tf32_hi_f(v.z); d[3] = tf32_hi_f(v.w);
        }
#pragma unroll
        for (int i = 0; i < 4; i++) {       // V tile 64x32, truncated at store
            int idx = tid + i * 128;
            int r = idx >> 3, c4 = (idx & 7) * 4;
            float4 v = *(const float4*)(Vb + base + (size_t)(n0 + r) * CC + c4);
            float* d = &Vs[r * 36 + c4];
            d[0] = tf32_hi_f(v.x); d[1] = tf32_hi_f(v.y);
            d[2] = tf32_hi_f(v.z); d[3] = tf32_hi_f(v.w);
        }
        __syncthreads();

        // S = Q K_hi^T  (2 MMAs per tile: qh + ql against truncated K)
        float s[8][4];
#pragma unroll
        for (int nt = 0; nt < 8; nt++) {
            s[nt][0] = s[nt][1] = s[nt][2] = s[nt][3] = 0.f;
        }
#pragma unroll
        for (int kc = 0; kc < 4; kc++) {
#pragma unroll
            for (int nt = 0; nt < 8; nt++) {
                int n = nt * 8 + grp;
                int col = kc * 8 + tig;
                unsigned kh0 = __float_as_uint(Ks[n * 36 + col]);
                unsigned kh1 = __float_as_uint(Ks[n * 36 + col + 4]);
                mma_tf32(s[nt], qh[kc][0], qh[kc][1], qh[kc][2], qh[kc][3], kh0, kh1);
                mma_tf32(s[nt], ql[kc][0], ql[kc][1], ql[kc][2], ql[kc][3], kh0, kh1);
            }
        }

        // online softmax (rows wr+grp and wr+grp+8)
        float tm0 = -INFINITY, tm1 = -INFINITY;
#pragma unroll
        for (int nt = 0; nt < 8; nt++) {
            tm0 = fmaxf(tm0, fmaxf(s[nt][0], s[nt][1]));
            tm1 = fmaxf(tm1, fmaxf(s[nt][2], s[nt][3]));
        }
        tm0 = fmaxf(tm0, __shfl_xor_sync(0xffffffff, tm0, 1));
        tm0 = fmaxf(tm0, __shfl_xor_sync(0xffffffff, tm0, 2));
        tm1 = fmaxf(tm1, __shfl_xor_sync(0xffffffff, tm1, 1));
        tm1 = fmaxf(tm1, __shfl_xor_sync(0xffffffff, tm1, 2));

        float mn0 = fmaxf(mr0, tm0), mn1 = fmaxf(mr1, tm1);
        float corr0 = __expf(mr0 - mn0), corr1 = __expf(mr1 - mn1);
        float ps0 = 0.f, ps1 = 0.f;
#pragma unroll
        for (int nt = 0; nt < 8; nt++) {
            float p0 = __expf(s[nt][0] - mn0);
            float p1 = __expf(s[nt][1] - mn0);
            float p2 = __expf(s[nt][2] - mn1);
            float p3 = __expf(s[nt][3] - mn1);
            ps0 += p0 + p1; ps1 += p2 + p3;   // l uses FULL p (as in R7)
            int row = wr + grp;
            int col = nt * 8 + tig * 2;
            // store truncated P for the PV MMA (bit-identical to hi-at-read)
            *(float2*)&Ps[row * 68 + col]       = make_float2(tf32_hi_f(p0), tf32_hi_f(p1));
            *(float2*)&Ps[(row + 8) * 68 + col] = make_float2(tf32_hi_f(p2), tf32_hi_f(p3));
        }
        ps0 += __shfl_xor_sync(0xffffffff, ps0, 1);
        ps0 += __shfl_xor_sync(0xffffffff, ps0, 2);
        ps1 += __shfl_xor_sync(0xffffffff, ps1, 1);
        ps1 += __shfl_xor_sync(0xffffffff, ps1, 2);
        l0 = l0 * corr0 + ps0;
        l1 = l1 * corr1 + ps1;
#pragma unroll
        for (int dt = 0; dt < 4; dt++) {
            oacc[dt][0] *= corr0; oacc[dt][1] *= corr0;
            oacc[dt][2] *= corr1; oacc[dt][3] *= corr1;
        }
        mr0 = mn0; mr1 = mn1;
        __syncwarp();

        // O += P_hi V_hi  (1 MMA per tile; operands already truncated in smem)
#pragma unroll
        for (int kc = 0; kc < 8; kc++) {
            int row = wr + grp;
            int col = kc * 8 + tig;
            unsigned ph0 = __float_as_uint(Ps[row * 68 + col]);
            unsigned ph1 = __float_as_uint(Ps[(row + 8) * 68 + col]);
            unsigned ph2 = __float_as_uint(Ps[row * 68 + col + 4]);
            unsigned ph3 = __float_as_uint(Ps[(row + 8) * 68 + col + 4]);
#pragma unroll
            for (int dt = 0; dt < 4; dt++) {
                unsigned vh0 = __float_as_uint(Vs[(kc * 8 + tig) * 36 + dt * 8 + grp]);
                unsigned vh1 = __float_as_uint(Vs[(kc * 8 + tig + 4) * 36 + dt * 8 + grp]);
                mma_tf32(oacc[dt], ph0, ph1, ph2, ph3, vh0, vh1);
            }
        }
        __syncwarp();
    }

    float inv0 = 1.0f / l0, inv1 = 1.0f / l1;
    int row = m0 + wr + grp;
#pragma unroll
    for (int dt = 0; dt < 4; dt++) {
        int col = dt * 8 + tig * 2;
        float2 v0 = { oacc[dt][0] * inv0, oacc[dt][1] * inv0 };
        float2 v1 = { oacc[dt][2] * inv1, oacc[dt][3] * inv1 };
        *(float2*)(O + base + (size_t)row * CC + col)       = v0;
        *(float2*)(O + base + (size_t)(row + 8) * CC + col) = v1;
    }
}

// ---------------- kernel 6: residual + LayerNorm ----------------
__global__ void ln_kernel(const float* __restrict__ P,
                          const float* __restrict__ X,
                          const float* __restrict__ g,
                          const float* __restrict__ beta,
                          float* __restrict__ E)
{
    int row = blockIdx.x;
    int c = threadIdx.x;
    size_t off = (size_t)row * CC + c;
    float y = P[off] + X[off];
    float v1 = y, v2 = y * y;
#pragma unroll
    for (int o = 16; o > 0; o >>= 1) {
        v1 += __shfl_xor_sync(0xffffffff, v1, o);
        v2 += __shfl_xor_sync(0xffffffff, v2, o);
    }
    __shared__ float s1[8], s2[8];
    int w = c >> 5, ln = c & 31;
    if (ln == 0) { s1[w] = v1; s2[w] = v2; }
    __syncthreads();
    float sum = 0.f, sq = 0.f;
#pragma unroll
    for (int i = 0; i < 8; i++) { sum += s1[i]; sq += s2[i]; }
    float mu  = sum * (1.0f / CC);
    float var = sq * (1.0f / CC) - mu * mu;
    float rs  = rsqrtf(var + 1e-5f);
    E[off] = (y - mu) * rs * g[c] + beta[c];
}

// ---------------- kernel 7: copy x -> out, overlay enhanced tokens ----------------
__global__ void scatter_kernel(const float* __restrict__ X,
                               const int* __restrict__ pos2k,
                               const float* __restrict__ E,
                               float* __restrict__ out)
{
    int gid = blockIdx.x * 256 + threadIdx.x;
    int b = gid >> 20;
    int c = (gid >> 12) & (CC - 1);
    int p = gid & (NN - 1);
    int k = pos2k[(b << 12) + p];
    float v = (k >= 0) ? E[(size_t)(((b << 10) + k) << 8) + c] : X[gid];
    out[gid] = v;
}

// ---------------- launch ----------------
extern "C" void kernel_launch(void* const* d_in, const int* in_sizes, int n_in,
                              void* d_out, int out_size)
{
    const float* x    = (const float*)d_in[0];
    const float* bmap = (const float*)d_in[1];
    const float* iw1  = (const float*)d_in[2];
    const float* ib1  = (const float*)d_in[3];
    const float* iw2  = (const float*)d_in[4];
    const float* ib2  = (const float*)d_in[5];
    const float* wq   = (const float*)d_in[6];
    const float* bq   = (const float*)d_in[7];
    const float* wk   = (const float*)d_in[8];
    const float* bk   = (const float*)d_in[9];
    const float* wv   = (const float*)d_in[10];
    const float* bv   = (const float*)d_in[11];
    const float* wo   = (const float*)d_in[12];
    const float* bo   = (const float*)d_in[13];
    const float* lng  = (const float*)d_in[14];
    const float* lnb  = (const float*)d_in[15];

    static float *P_imp = nullptr, *P_xsp, *P_q, *P_k, *P_v, *P_ao, *P_ps, *P_enh;
    static int *P_topidx, *P_pos2k;
    if (!P_imp) {
        cudaGetSymbolAddress((void**)&P_imp,    g_imp);
        cudaGetSymbolAddress((void**)&P_topidx, g_topidx);
        cudaGetSymbolAddress((void**)&P_pos2k,  g_pos2k);
        cudaGetSymbolAddress((void**)&P_xsp,    g_xsp);
        cudaGetSymbolAddress((void**)&P_q,      g_q);
        cudaGetSymbolAddress((void**)&P_k,      g_k);
        cudaGetSymbolAddress((void**)&P_v,      g_v);
        cudaGetSymbolAddress((void**)&P_ao,     g_ao);
        cudaGetSymbolAddress((void**)&P_ps,     g_ps);
        cudaGetSymbolAddress((void**)&P_enh,    g_enh);
    }

    float* out = (float*)d_out;
    float* imp_out = (out_size >= BB * CC * NN + BB * NN) ? out + (size_t)BB * CC * NN
                                                          : nullptr;

    importance_mma_kernel<<<BB * 32, 256>>>(x, bmap, iw1, ib1, iw2, ib2,
                                            P_imp, imp_out);
    topk_kernel<<<BB, 1024>>>(P_imp, P_topidx, P_pos2k);

    dim3 ggrid_gather(KK / 32, CC / 32, BB);
    gather_kernel<<<ggrid_gather, 256>>>(x, P_topidx, P_xsp);

    // fused QKV projections (grid.z selects weight set)
    dim3 ggrid3(CC / 64, (BB * KK) / 128, 3);
    gemm_tf32_kernel<<<ggrid3, 256>>>(P_xsp,
                                      wq, bq, P_q,
                                      wk, bk, P_k,
                                      wv, bv, P_v,
                                      BB * KK, CC, CC);

    dim3 agrid(KK / 64, NH, BB);
    attn_tf32_kernel<<<agrid, 128>>>(P_q, P_k, P_v, P_ao);

    dim3 ggrid1(CC / 64, (BB * KK) / 128, 1);
    gemm_tf32_kernel<<<ggrid1, 256>>>(P_ao,
                                      wo, bo, P_ps,
                                      wo, bo, P_ps,
                                      wo, bo, P_ps,
                                      BB * KK, CC, CC);

    ln_kernel<<<BB * KK, 256>>>(P_ps, P_xsp, lng, lnb, P_enh);
    scatter_kernel<<<(BB * CC * NN) / 256, 256>>>(x, P_pos2k, P_enh, out);
}

// round 10
// speedup vs baseline: 2.1975x; 1.0333x over previous
#include <cuda_runtime.h>
#include <math.h>

// Problem constants
#define BB   8
#define CC   256
#define NN   4096          // H*W
#define KK   1024          // top-K
#define NH   8
#define HD   32
#define CH   64            // importance hidden

// ---------------- scratch (device globals; no allocation) ----------------
__device__ float g_imp  [BB * NN];
__device__ int   g_topidx[BB * KK];
__device__ int   g_pos2k [BB * NN];
__device__ float g_xsp  [BB * KK * CC];
__device__ float g_q    [BB * KK * CC];
__device__ float g_k    [BB * KK * CC];
__device__ float g_v    [BB * KK * CC];
__device__ float g_ao   [BB * KK * CC];
__device__ float g_ps   [BB * KK * CC];
__device__ float g_enh  [BB * KK * CC];

// ---------------- tf32 mma helpers ----------------
__device__ __forceinline__ void mma_tf32(float* d,
                                         unsigned a0, unsigned a1, unsigned a2, unsigned a3,
                                         unsigned b0, unsigned b1)
{
    asm volatile(
        "mma.sync.aligned.m16n8k8.row.col.f32.tf32.tf32.f32 "
        "{%0,%1,%2,%3}, {%4,%5,%6,%7}, {%8,%9}, {%0,%1,%2,%3};\n"
        : "+f"(d[0]), "+f"(d[1]), "+f"(d[2]), "+f"(d[3])
        : "r"(a0), "r"(a1), "r"(a2), "r"(a3), "r"(b0), "r"(b1));
}

// exact split: x = hi + lo, both exactly representable in tf32
__device__ __forceinline__ void tf32_split(float x, unsigned& hi, unsigned& lo)
{
    unsigned h = __float_as_uint(x) & 0xFFFFE000u;
    hi = h;
    lo = __float_as_uint(x - __uint_as_float(h));
}

__device__ __forceinline__ float tf32_hi_f(float x)
{
    return __uint_as_float(__float_as_uint(x) & 0xFFFFE000u);
}

// ---------------- kernel 1: importance net (tf32-split MMA, 3-term EXACT) ----------------
// Top-K selection depends on this — keep full fp32-equivalent accuracy.
__global__ void importance_mma_kernel(const float* __restrict__ x,
                                      const float* __restrict__ bmap,
                                      const float* __restrict__ w1,
                                      const float* __restrict__ b1,
                                      const float* __restrict__ w2,
                                      const float* __restrict__ b2,
                                      float* __restrict__ imp,
                                      float* __restrict__ imp_out)
{
    __shared__ union {
        struct { float As[32 * 132]; float Ws[64 * 36]; } t;   // GEMM tiles
        float Hs[128 * 65];                                     // gelu(h) overlay
    } u;
    __shared__ float b1s[64], w2s[64];

    int tid  = threadIdx.x;   // 256
    int lane = tid & 31;
    int warp = tid >> 5;
    int wm = warp >> 1;
    int wn = warp & 1;
    int grp = lane >> 2;
    int tig = lane & 3;

    int b  = blockIdx.x >> 5;
    int p0 = (blockIdx.x & 31) * 128;

    if (tid < 64) { b1s[tid] = b1[tid]; w2s[tid] = w2[tid]; }

    float acc[2][4][4];
#pragma unroll
    for (int mt = 0; mt < 2; mt++)
#pragma unroll
        for (int nt = 0; nt < 4; nt++)
#pragma unroll
            for (int j = 0; j < 4; j++) acc[mt][nt][j] = 0.f;

    for (int c0 = 0; c0 < CC; c0 += 32) {
        __syncthreads();
        // A tile: 32 channels x 128 pixels, coalesced along p
#pragma unroll
        for (int i = 0; i < 4; i++) {
            int idx = tid + i * 256;
            int cl = idx >> 5, p4 = (idx & 31) * 4;
            float4 v = *(const float4*)(x + (((size_t)(b * CC + c0 + cl)) << 12) + p0 + p4);
            float* d = &u.t.As[cl * 132 + p4];
            d[0] = v.x; d[1] = v.y; d[2] = v.z; d[3] = v.w;
        }
        // W tile: 64 j x 32 channels
#pragma unroll
        for (int i = 0; i < 2; i++) {
            int idx = tid + i * 256;
            int j = idx >> 3, c4 = (idx & 7) * 4;
            float4 v = *(const float4*)(w1 + j * CC + c0 + c4);
            float* d = &u.t.Ws[j * 36 + c4];
            d[0] = v.x; d[1] = v.y; d[2] = v.z; d[3] = v.w;
        }
        __syncthreads();

#pragma unroll
        for (int kc = 0; kc < 4; kc++) {
            unsigned ah[2][4], al[2][4];
#pragma unroll
            for (int mt = 0; mt < 2; mt++) {
                int row = wm * 32 + mt * 16 + grp;
                int col = kc * 8 + tig;
                tf32_split(u.t.As[col * 132 + row],           ah[mt][0], al[mt][0]);
                tf32_split(u.t.As[col * 132 + row + 8],       ah[mt][1], al[mt][1]);
                tf32_split(u.t.As[(col + 4) * 132 + row],     ah[mt][2], al[mt][2]);
                tf32_split(u.t.As[(col + 4) * 132 + row + 8], ah[mt][3], al[mt][3]);
            }
#pragma unroll
            for (int nt = 0; nt < 4; nt++) {
                int n = wn * 32 + nt * 8 + grp;
                int col = kc * 8 + tig;
                unsigned bh0, bl0, bh1, bl1;
                tf32_split(u.t.Ws[n * 36 + col],     bh0, bl0);
                tf32_split(u.t.Ws[n * 36 + col + 4], bh1, bl1);
#pragma unroll
                for (int mt = 0; mt < 2; mt++) {
                    mma_tf32(acc[mt][nt], ah[mt][0], ah[mt][1], ah[mt][2], ah[mt][3], bh0, bh1);
                    mma_tf32(acc[mt][nt], ah[mt][0], ah[mt][1], ah[mt][2], ah[mt][3], bl0, bl1);
                    mma_tf32(acc[mt][nt], al[mt][0], al[mt][1], al[mt][2], al[mt][3], bh0, bh1);
                }
            }
        }
    }
    __syncthreads();

    // epilogue: bias + exact GELU into smem
#pragma unroll
    for (int mt = 0; mt < 2; mt++) {
#pragma unroll
        for (int nt = 0; nt < 4; nt++) {
#pragma unroll
            for (int j = 0; j < 4; j++) {
                int row = wm * 32 + mt * 16 + grp + ((j >= 2) ? 8 : 0);
                int col = wn * 32 + nt * 8 + tig * 2 + (j & 1);
                float v = acc[mt][nt][j] + b1s[col];
                u.Hs[row * 65 + col] = 0.5f * v * (1.0f + erff(v * 0.70710678118654752f));
            }
        }
    }
    __syncthreads();

    // reduce 64 hidden per row (2 threads per row), sigmoid + boundary
    int row = tid >> 1;
    int jh  = (tid & 1) * 32;
    float s = 0.f;
#pragma unroll
    for (int jj = 0; jj < 32; jj++) s += u.Hs[row * 65 + jh + jj] * w2s[jh + jj];
    s += __shfl_xor_sync(0xffffffff, s, 1);
    if ((tid & 1) == 0) {
        float acc2 = s + b2[0];
        float sg  = 1.0f / (1.0f + __expf(-acc2));
        float val = sg + 0.5f * bmap[(b << 12) + p0 + row];
        imp[(b << 12) + p0 + row] = val;
        if (imp_out) imp_out[(b << 12) + p0 + row] = val;
    }
}

// ---------------- kernel 2: exact top-K via bitonic sort ----------------
__global__ void topk_kernel(const float* __restrict__ imp,
                            int* __restrict__ topidx,
                            int* __restrict__ pos2k)
{
    __shared__ unsigned long long keys[NN];
    __shared__ int idxs[KK];
    int tid = threadIdx.x;  // 1024
    int b = blockIdx.x;

    for (int i = tid; i < NN; i += 1024) {
        unsigned int fb = __float_as_uint(imp[(b << 12) + i]);
        keys[i] = ((unsigned long long)fb << 32) | (unsigned int)(NN - 1 - i);
        pos2k[(b << 12) + i] = -1;
    }
    __syncthreads();

    for (int k2 = 2; k2 <= NN; k2 <<= 1) {
        for (int j = k2 >> 1; j > 0; j >>= 1) {
            for (int t = tid; t < NN; t += 1024) {
                int ixj = t ^ j;
                if (ixj > t) {
                    unsigned long long a = keys[t], c = keys[ixj];
                    if ((a < c) == ((t & k2) == 0)) { keys[t] = c; keys[ixj] = a; }
                }
            }
            __syncthreads();
        }
    }
    idxs[tid] = (NN - 1) - (int)(keys[tid] & 0xFFFFFFFFull);
    __syncthreads();
    for (int k2 = 2; k2 <= KK; k2 <<= 1) {
        for (int j = k2 >> 1; j > 0; j >>= 1) {
            int ixj = tid ^ j;
            if (ixj > tid) {
                int a = idxs[tid], c = idxs[ixj];
                if ((a > c) == ((tid & k2) == 0)) { idxs[tid] = c; idxs[ixj] = a; }
            }
            __syncthreads();
        }
    }
    int p = idxs[tid];
    topidx[(b << 10) + tid] = p;
    pos2k[(b << 12) + p] = tid;
}

// ---------------- kernel 3: gather via smem transpose ----------------
__global__ void gather_kernel(const float* __restrict__ x,
                              const int* __restrict__ topidx,
                              float* __restrict__ xsp)
{
    __shared__ float sm[32][33];
    int k0 = blockIdx.x * 32;
    int c0 = blockIdx.y * 32;
    int b  = blockIdx.z;
    int tid = threadIdx.x;
    int l = tid & 31, g = tid >> 5;

    int p = topidx[(b << 10) + k0 + l];
#pragma unroll
    for (int r = 0; r < 4; r++) {
        int cl = g + r * 8;
        sm[cl][l] = x[(((size_t)(b * CC + c0 + cl)) << 12) + p];
    }
    __syncthreads();
#pragma unroll
    for (int r = 0; r < 4; r++) {
        int kl = g + r * 8;
        xsp[(((size_t)((b << 10) + k0 + kl)) << 8) + c0 + l] = sm[l][kl];
    }
}

// ---------------- kernel 4: 2-term tf32 GEMM, W pre-split in smem ----------------
// A truncated at store. W stored as (hi, lo) pair -> inner loop has NO split math:
// per (kc,nt): 4 LDS + 4 MMA. Bit-identical to splitting at read.
__global__ void gemm_tf32_kernel(const float* __restrict__ A,
                                 const float* __restrict__ W0, const float* __restrict__ B0, float* __restrict__ C0,
                                 const float* __restrict__ W1, const float* __restrict__ B1, float* __restrict__ C1,
                                 const float* __restrict__ W2, const float* __restrict__ B2, float* __restrict__ C2,
                                 int M, int Nn, int Kd)
{
    const float* W    = W0;
    const float* bias = B0;
    float*       Cout = C0;
    if (blockIdx.z == 1)      { W = W1; bias = B1; Cout = C1; }
    else if (blockIdx.z == 2) { W = W2; bias = B2; Cout = C2; }

    __shared__ float As[128 * 36];
    __shared__ float Wh[64 * 36];
    __shared__ float Wl[64 * 36];

    int tid  = threadIdx.x;
    int lane = tid & 31;
    int warp = tid >> 5;
    int wm = warp >> 1;
    int wn = warp & 1;
    int grp = lane >> 2;
    int tig = lane & 3;

    int bm = blockIdx.y * 128;
    int bn = blockIdx.x * 64;

    float acc[2][4][4];
#pragma unroll
    for (int mt = 0; mt < 2; mt++)
#pragma unroll
        for (int nt = 0; nt < 4; nt++)
#pragma unroll
            for (int j = 0; j < 4; j++) acc[mt][nt][j] = 0.f;

    float4 ra[4], rw[2];
#pragma unroll
    for (int i = 0; i < 4; i++) {
        int idx = tid + i * 256;
        int r = idx >> 3, c4 = (idx & 7) * 4;
        ra[i] = *(const float4*)(A + (size_t)(bm + r) * Kd + c4);
    }
#pragma unroll
    for (int i = 0; i < 2; i++) {
        int idx = tid + i * 256;
        int r = idx >> 3, c4 = (idx & 7) * 4;
        rw[i] = *(const float4*)(W + (size_t)(bn + r) * Kd + c4);
    }

    for (int c0 = 0; c0 < Kd; c0 += 32) {
        // commit current chunk (A truncated; W split hi/lo)
#pragma unroll
        for (int i = 0; i < 4; i++) {
            int idx = tid + i * 256;
            int r = idx >> 3, c4 = (idx & 7) * 4;
            float* d = &As[r * 36 + c4];
            d[0] = tf32_hi_f(ra[i].x); d[1] = tf32_hi_f(ra[i].y);
            d[2] = tf32_hi_f(ra[i].z); d[3] = tf32_hi_f(ra[i].w);
        }
#pragma unroll
        for (int i = 0; i < 2; i++) {
            int idx = tid + i * 256;
            int r = idx >> 3, c4 = (idx & 7) * 4;
            float h0 = tf32_hi_f(rw[i].x), h1 = tf32_hi_f(rw[i].y);
            float h2 = tf32_hi_f(rw[i].z), h3 = tf32_hi_f(rw[i].w);
            float* dh = &Wh[r * 36 + c4];
            float* dl = &Wl[r * 36 + c4];
            dh[0] = h0; dh[1] = h1; dh[2] = h2; dh[3] = h3;
            dl[0] = rw[i].x - h0; dl[1] = rw[i].y - h1;
            dl[2] = rw[i].z - h2; dl[3] = rw[i].w - h3;
        }
        __syncthreads();

        // prefetch next chunk (overlaps MMA below)
        if (c0 + 32 < Kd) {
#pragma unroll
            for (int i = 0; i < 4; i++) {
                int idx = tid + i * 256;
                int r = idx >> 3, c4 = (idx & 7) * 4;
                ra[i] = *(const float4*)(A + (size_t)(bm + r) * Kd + c0 + 32 + c4);
            }
#pragma unroll
            for (int i = 0; i < 2; i++) {
                int idx = tid + i * 256;
                int r = idx >> 3, c4 = (idx & 7) * 4;
                rw[i] = *(const float4*)(W + (size_t)(bn + r) * Kd + c0 + 32 + c4);
            }
        }

#pragma unroll
        for (int kc = 0; kc < 4; kc++) {
            unsigned ah[2][4];
#pragma unroll
            for (int mt = 0; mt < 2; mt++) {
                int row = wm * 32 + mt * 16 + grp;
                int col = kc * 8 + tig;
                ah[mt][0] = __float_as_uint(As[row * 36 + col]);
                ah[mt][1] = __float_as_uint(As[(row + 8) * 36 + col]);
                ah[mt][2] = __float_as_uint(As[row * 36 + col + 4]);
                ah[mt][3] = __float_as_uint(As[(row + 8) * 36 + col + 4]);
            }
#pragma unroll
            for (int nt = 0; nt < 4; nt++) {
                int n = wn * 32 + nt * 8 + grp;
                int col = kc * 8 + tig;
                unsigned bh0 = __float_as_uint(Wh[n * 36 + col]);
                unsigned bh1 = __float_as_uint(Wh[n * 36 + col + 4]);
                unsigned bl0 = __float_as_uint(Wl[n * 36 + col]);
                unsigned bl1 = __float_as_uint(Wl[n * 36 + col + 4]);
#pragma unroll
                for (int mt = 0; mt < 2; mt++) {
                    mma_tf32(acc[mt][nt], ah[mt][0], ah[mt][1], ah[mt][2], ah[mt][3], bh0, bh1);
                    mma_tf32(acc[mt][nt], ah[mt][0], ah[mt][1], ah[mt][2], ah[mt][3], bl0, bl1);
                }
            }
        }
        __syncthreads();
    }

#pragma unroll
    for (int mt = 0; mt < 2; mt++) {
#pragma unroll
        for (int nt = 0; nt < 4; nt++) {
            int row = bm + wm * 32 + mt * 16 + grp;
            int col = bn + wn * 32 + nt * 8 + tig * 2;
            float2 bv = *(const float2*)(bias + col);
            float2 v0 = { acc[mt][nt][0] + bv.x, acc[mt][nt][1] + bv.y };
            float2 v1 = { acc[mt][nt][2] + bv.x, acc[mt][nt][3] + bv.y };
            *(float2*)(Cout + (size_t)row * Nn + col)       = v0;
            *(float2*)(Cout + (size_t)(row + 8) * Nn + col) = v1;
        }
    }
}

// ---------------- kernel 5: flash attention ----------------
// QK: 1 MMA (Q and K both truncated). PV: 1 MMA (P, V truncated).
// K/V register prefetch: next tile's gmem loads overlap MMA/softmax.
__global__ void attn_tf32_kernel(const float* __restrict__ Q,
                                 const float* __restrict__ Kb,
                                 const float* __restrict__ Vb,
                                 float* __restrict__ O)
{
    __shared__ float Ks[64 * 36];
    __shared__ float Vs[64 * 36];
    __shared__ float Ps[64 * 68];

    int tid  = threadIdx.x;   // 128
    int lane = tid & 31;
    int warp = tid >> 5;
    int grp = lane >> 2;
    int tig = lane & 3;
    int wr = warp * 16;

    int m0 = blockIdx.x * 64;
    int hh = blockIdx.y;
    int b  = blockIdx.z;
    size_t base = (size_t)b * KK * CC + hh * HD;
    const float scale = 0.17677669529663687f;  // 1/sqrt(32)

    // stage Q tile: pre-scaled AND truncated (QK uses truncated Q now)
#pragma unroll
    for (int i = 0; i < 4; i++) {
        int idx = tid + i * 128;
        int r = idx >> 3, c4 = (idx & 7) * 4;
        float4 v = *(const float4*)(Q + base + (size_t)(m0 + r) * CC + c4);
        float* d = &Ps[r * 36 + c4];
        d[0] = tf32_hi_f(v.x * scale); d[1] = tf32_hi_f(v.y * scale);
        d[2] = tf32_hi_f(v.z * scale); d[3] = tf32_hi_f(v.w * scale);
    }
    __syncthreads();

    unsigned qf[4][4];
#pragma unroll
    for (int kc = 0; kc < 4; kc++) {
        int row = wr + grp;
        int col = kc * 8 + tig;
        qf[kc][0] = __float_as_uint(Ps[row * 36 + col]);
        qf[kc][1] = __float_as_uint(Ps[(row + 8) * 36 + col]);
        qf[kc][2] = __float_as_uint(Ps[row * 36 + col + 4]);
        qf[kc][3] = __float_as_uint(Ps[(row + 8) * 36 + col + 4]);
    }
    __syncthreads();

    float mr0 = -INFINITY, mr1 = -INFINITY, l0 = 0.f, l1 = 0.f;
    float oacc[4][4];
#pragma unroll
    for (int dt = 0; dt < 4; dt++)
#pragma unroll
        for (int j = 0; j < 4; j++) oacc[dt][j] = 0.f;

    // prologue: tile 0 into registers
    float4 rk[4], rv[4];
#pragma unroll
    for (int i = 0; i < 4; i++) {
        int idx = tid + i * 128;
        int r = idx >> 3, c4 = (idx & 7) * 4;
        rk[i] = *(const float4*)(Kb + base + (size_t)r * CC + c4);
        rv[i] = *(const float4*)(Vb + base + (size_t)r * CC + c4);
    }

    for (int n0 = 0; n0 < KK; n0 += 64) {
        __syncthreads();   // previous iteration's consumers done with Ks/Vs
        // commit current tile (truncated at store)
#pragma unroll
        for (int i = 0; i < 4; i++) {
            int idx = tid + i * 128;
            int r = idx >> 3, c4 = (idx & 7) * 4;
            float* dk = &Ks[r * 36 + c4];
            dk[0] = tf32_hi_f(rk[i].x); dk[1] = tf32_hi_f(rk[i].y);
            dk[2] = tf32_hi_f(rk[i].z); dk[3] = tf32_hi_f(rk[i].w);
            float* dv = &Vs[r * 36 + c4];
            dv[0] = tf32_hi_f(rv[i].x); dv[1] = tf32_hi_f(rv[i].y);
            dv[2] = tf32_hi_f(rv[i].z); dv[3] = tf32_hi_f(rv[i].w);
        }
        __syncthreads();

        // prefetch next tile (overlaps MMA/softmax below)
        if (n0 + 64 < KK) {
#pragma unroll
            for (int i = 0; i < 4; i++) {
                int idx = tid + i * 128;
                int r = idx >> 3, c4 = (idx & 7) * 4;
                rk[i] = *(const float4*)(Kb + base + (size_t)(n0 + 64 + r) * CC + c4);
                rv[i] = *(const float4*)(Vb + base + (size_t)(n0 + 64 + r) * CC + c4);
            }
        }

        // S = Q_hi K_hi^T  (1 MMA per tile)
        float s[8][4];
#pragma unroll
        for (int nt = 0; nt < 8; nt++) {
            s[nt][0] = s[nt][1] = s[nt][2] = s[nt][3] = 0.f;
        }
#pragma unroll
        for (int kc = 0; kc < 4; kc++) {
#pragma unroll
            for (int nt = 0; nt < 8; nt++) {
                int n = nt * 8 + grp;
                int col = kc * 8 + tig;
                unsigned kh0 = __float_as_uint(Ks[n * 36 + col]);
                unsigned kh1 = __float_as_uint(Ks[n * 36 + col + 4]);
                mma_tf32(s[nt], qf[kc][0], qf[kc][1], qf[kc][2], qf[kc][3], kh0, kh1);
            }
        }

        // online softmax (rows wr+grp and wr+grp+8)
        float tm0 = -INFINITY, tm1 = -INFINITY;
#pragma unroll
        for (int nt = 0; nt < 8; nt++) {
            tm0 = fmaxf(tm0, fmaxf(s[nt][0], s[nt][1]));
            tm1 = fmaxf(tm1, fmaxf(s[nt][2], s[nt][3]));
        }
        tm0 = fmaxf(tm0, __shfl_xor_sync(0xffffffff, tm0, 1));
        tm0 = fmaxf(tm0, __shfl_xor_sync(0xffffffff, tm0, 2));
        tm1 = fmaxf(tm1, __shfl_xor_sync(0xffffffff, tm1, 1));
        tm1 = fmaxf(tm1, __shfl_xor_sync(0xffffffff, tm1, 2));

        float mn0 = fmaxf(mr0, tm0), mn1 = fmaxf(mr1, tm1);
        float corr0 = __expf(mr0 - mn0), corr1 = __expf(mr1 - mn1);
        float ps0 = 0.f, ps1 = 0.f;
#pragma unroll
        for (int nt = 0; nt < 8; nt++) {
            float p0 = __expf(s[nt][0] - mn0);
            float p1 = __expf(s[nt][1] - mn0);
            float p2 = __expf(s[nt][2] - mn1);
            float p3 = __expf(s[nt][3] - mn1);
            ps0 += p0 + p1; ps1 += p2 + p3;   // l uses FULL p
            int row = wr + grp;
            int col = nt * 8 + tig * 2;
            *(float2*)&Ps[row * 68 + col]       = make_float2(tf32_hi_f(p0), tf32_hi_f(p1));
            *(float2*)&Ps[(row + 8) * 68 + col] = make_float2(tf32_hi_f(p2), tf32_hi_f(p3));
        }
        ps0 += __shfl_xor_sync(0xffffffff, ps0, 1);
        ps0 += __shfl_xor_sync(0xffffffff, ps0, 2);
        ps1 += __shfl_xor_sync(0xffffffff, ps1, 1);
        ps1 += __shfl_xor_sync(0xffffffff, ps1, 2);
        l0 = l0 * corr0 + ps0;
        l1 = l1 * corr1 + ps1;
#pragma unroll
        for (int dt = 0; dt < 4; dt++) {
            oacc[dt][0] *= corr0; oacc[dt][1] *= corr0;
            oacc[dt][2] *= corr1; oacc[dt][3] *= corr1;
        }
        mr0 = mn0; mr1 = mn1;
        __syncwarp();

        // O += P_hi V_hi  (1 MMA per tile)
#pragma unroll
        for (int kc = 0; kc < 8; kc++) {
            int row = wr + grp;
            int col = kc * 8 + tig;
            unsigned ph0 = __float_as_uint(Ps[row * 68 + col]);
            unsigned ph1 = __float_as_uint(Ps[(row + 8) * 68 + col]);
            unsigned ph2 = __float_as_uint(Ps[row * 68 + col + 4]);
            unsigned ph3 = __float_as_uint(Ps[(row + 8) * 68 + col + 4]);
#pragma unroll
            for (int dt = 0; dt < 4; dt++) {
                unsigned vh0 = __float_as_uint(Vs[(kc * 8 + tig) * 36 + dt * 8 + grp]);
                unsigned vh1 = __float_as_uint(Vs[(kc * 8 + tig + 4) * 36 + dt * 8 + grp]);
                mma_tf32(oacc[dt], ph0, ph1, ph2, ph3, vh0, vh1);
            }
        }
        __syncwarp();
    }

    float inv0 = 1.0f / l0, inv1 = 1.0f / l1;
    int row = m0 + wr + grp;
#pragma unroll
    for (int dt = 0; dt < 4; dt++) {
        int col = dt * 8 + tig * 2;
        float2 v0 = { oacc[dt][0] * inv0, oacc[dt][1] * inv0 };
        float2 v1 = { oacc[dt][2] * inv1, oacc[dt][3] * inv1 };
        *(float2*)(O + base + (size_t)row * CC + col)       = v0;
        *(float2*)(O + base + (size_t)(row + 8) * CC + col) = v1;
    }
}

// ---------------- kernel 6: residual + LayerNorm ----------------
__global__ void ln_kernel(const float* __restrict__ P,
                          const float* __restrict__ X,
                          const float* __restrict__ g,
                          const float* __restrict__ beta,
                          float* __restrict__ E)
{
    int row = blockIdx.x;
    int c = threadIdx.x;
    size_t off = (size_t)row * CC + c;
    float y = P[off] + X[off];
    float v1 = y, v2 = y * y;
#pragma unroll
    for (int o = 16; o > 0; o >>= 1) {
        v1 += __shfl_xor_sync(0xffffffff, v1, o);
        v2 += __shfl_xor_sync(0xffffffff, v2, o);
    }
    __shared__ float s1[8], s2[8];
    int w = c >> 5, ln = c & 31;
    if (ln == 0) { s1[w] = v1; s2[w] = v2; }
    __syncthreads();
    float sum = 0.f, sq = 0.f;
#pragma unroll
    for (int i = 0; i < 8; i++) { sum += s1[i]; sq += s2[i]; }
    float mu  = sum * (1.0f / CC);
    float var = sq * (1.0f / CC) - mu * mu;
    float rs  = rsqrtf(var + 1e-5f);
    E[off] = (y - mu) * rs * g[c] + beta[c];
}

// ---------------- kernel 7: copy x -> out, overlay enhanced tokens ----------------
__global__ void scatter_kernel(const float* __restrict__ X,
                               const int* __restrict__ pos2k,
                               const float* __restrict__ E,
                               float* __restrict__ out)
{
    int gid = blockIdx.x * 256 + threadIdx.x;
    int b = gid >> 20;
    int c = (gid >> 12) & (CC - 1);
    int p = gid & (NN - 1);
    int k = pos2k[(b << 12) + p];
    float v = (k >= 0) ? E[(size_t)(((b << 10) + k) << 8) + c] : X[gid];
    out[gid] = v;
}

// ---------------- launch ----------------
extern "C" void kernel_launch(void* const* d_in, const int* in_sizes, int n_in,
                              void* d_out, int out_size)
{
    const float* x    = (const float*)d_in[0];
    const float* bmap = (const float*)d_in[1];
    const float* iw1  = (const float*)d_in[2];
    const float* ib1  = (const float*)d_in[3];
    const float* iw2  = (const float*)d_in[4];
    const float* ib2  = (const float*)d_in[5];
    const float* wq   = (const float*)d_in[6];
    const float* bq   = (const float*)d_in[7];
    const float* wk   = (const float*)d_in[8];
    const float* bk   = (const float*)d_in[9];
    const float* wv   = (const float*)d_in[10];
    const float* bv   = (const float*)d_in[11];
    const float* wo   = (const float*)d_in[12];
    const float* bo   = (const float*)d_in[13];
    const float* lng  = (const float*)d_in[14];
    const float* lnb  = (const float*)d_in[15];

    static float *P_imp = nullptr, *P_xsp, *P_q, *P_k, *P_v, *P_ao, *P_ps, *P_enh;
    static int *P_topidx, *P_pos2k;
    if (!P_imp) {
        cudaGetSymbolAddress((void**)&P_imp,    g_imp);
        cudaGetSymbolAddress((void**)&P_topidx, g_topidx);
        cudaGetSymbolAddress((void**)&P_pos2k,  g_pos2k);
        cudaGetSymbolAddress((void**)&P_xsp,    g_xsp);
        cudaGetSymbolAddress((void**)&P_q,      g_q);
        cudaGetSymbolAddress((void**)&P_k,      g_k);
        cudaGetSymbolAddress((void**)&P_v,      g_v);
        cudaGetSymbolAddress((void**)&P_ao,     g_ao);
        cudaGetSymbolAddress((void**)&P_ps,     g_ps);
        cudaGetSymbolAddress((void**)&P_enh,    g_enh);
    }

    float* out = (float*)d_out;
    float* imp_out = (out_size >= BB * CC * NN + BB * NN) ? out + (size_t)BB * CC * NN
                                                          : nullptr;

    importance_mma_kernel<<<BB * 32, 256>>>(x, bmap, iw1, ib1, iw2, ib2,
                                            P_imp, imp_out);
    topk_kernel<<<BB, 1024>>>(P_imp, P_topidx, P_pos2k);

    dim3 ggrid_gather(KK / 32, CC / 32, BB);
    gather_kernel<<<ggrid_gather, 256>>>(x, P_topidx, P_xsp);

    // fused QKV projections (grid.z selects weight set)
    dim3 ggrid3(CC / 64, (BB * KK) / 128, 3);
    gemm_tf32_kernel<<<ggrid3, 256>>>(P_xsp,
                                      wq, bq, P_q,
                                      wk, bk, P_k,
                                      wv, bv, P_v,
                                      BB * KK, CC, CC);

    dim3 agrid(KK / 64, NH, BB);
    attn_tf32_kernel<<<agrid, 128>>>(P_q, P_k, P_v, P_ao);

    dim3 ggrid1(CC / 64, (BB * KK) / 128, 1);
    gemm_tf32_kernel<<<ggrid1, 256>>>(P_ao,
                                      wo, bo, P_ps,
                                      wo, bo, P_ps,
                                      wo, bo, P_ps,
                                      BB * KK, CC, CC);

    ln_kernel<<<BB * KK, 256>>>(P_ps, P_xsp, lng, lnb, P_enh);
    scatter_kernel<<<(BB * CC * NN) / 256, 256>>>(x, P_pos2k, P_enh, out);
}

// round 11
// speedup vs baseline: 2.5284x; 1.1506x over previous
#include <cuda_runtime.h>
#include <math.h>

// Problem constants
#define BB   8
#define CC   256
#define NN   4096          // H*W
#define KK   1024          // top-K
#define NH   8
#define HD   32
#define CH   64            // importance hidden

// ---------------- scratch (device globals; no allocation) ----------------
__device__ float g_imp  [BB * NN];
__device__ int   g_topidx[BB * KK];
__device__ int   g_pos2k [BB * NN];
__device__ float g_xsp  [BB * KK * CC];
__device__ float g_q    [BB * KK * CC];
__device__ float g_k    [BB * KK * CC];
__device__ float g_v    [BB * KK * CC];
__device__ float g_ao   [BB * KK * CC];
__device__ float g_ps   [BB * KK * CC];
__device__ float g_enh  [BB * KK * CC];

// ---------------- mma helpers ----------------
__device__ __forceinline__ void mma_tf32(float* d,
                                         unsigned a0, unsigned a1, unsigned a2, unsigned a3,
                                         unsigned b0, unsigned b1)
{
    asm volatile(
        "mma.sync.aligned.m16n8k8.row.col.f32.tf32.tf32.f32 "
        "{%0,%1,%2,%3}, {%4,%5,%6,%7}, {%8,%9}, {%0,%1,%2,%3};\n"
        : "+f"(d[0]), "+f"(d[1]), "+f"(d[2]), "+f"(d[3])
        : "r"(a0), "r"(a1), "r"(a2), "r"(a3), "r"(b0), "r"(b1));
}

__device__ __forceinline__ void mma_bf16(float* d,
                                         unsigned a0, unsigned a1, unsigned a2, unsigned a3,
                                         unsigned b0, unsigned b1)
{
    asm volatile(
        "mma.sync.aligned.m16n8k16.row.col.f32.bf16.bf16.f32 "
        "{%0,%1,%2,%3}, {%4,%5,%6,%7}, {%8,%9}, {%0,%1,%2,%3};\n"
        : "+f"(d[0]), "+f"(d[1]), "+f"(d[2]), "+f"(d[3])
        : "r"(a0), "r"(a1), "r"(a2), "r"(a3), "r"(b0), "r"(b1));
}

// exact split: x = hi + lo, both exactly representable in tf32
__device__ __forceinline__ void tf32_split(float x, unsigned& hi, unsigned& lo)
{
    unsigned h = __float_as_uint(x) & 0xFFFFE000u;
    hi = h;
    lo = __float_as_uint(x - __uint_as_float(h));
}

__device__ __forceinline__ float tf32_hi_f(float x)
{
    return __uint_as_float(__float_as_uint(x) & 0xFFFFE000u);
}

// pack two floats to bf16x2: low half = lo (even-k element), high half = hi
__device__ __forceinline__ unsigned pack_bf16x2(float lo, float hi)
{
    unsigned r;
    asm("cvt.rn.bf16x2.f32 %0, %1, %2;" : "=r"(r) : "f"(hi), "f"(lo));
    return r;
}

// ---------------- kernel 1: importance net (tf32-split MMA, 3-term EXACT) ----------------
// Top-K selection depends on this — keep full fp32-equivalent accuracy.
__global__ void importance_mma_kernel(const float* __restrict__ x,
                                      const float* __restrict__ bmap,
                                      const float* __restrict__ w1,
                                      const float* __restrict__ b1,
                                      const float* __restrict__ w2,
                                      const float* __restrict__ b2,
                                      float* __restrict__ imp,
                                      float* __restrict__ imp_out)
{
    __shared__ union {
        struct { float As[32 * 132]; float Ws[64 * 36]; } t;   // GEMM tiles
        float Hs[128 * 65];                                     // gelu(h) overlay
    } u;
    __shared__ float b1s[64], w2s[64];

    int tid  = threadIdx.x;   // 256
    int lane = tid & 31;
    int warp = tid >> 5;
    int wm = warp >> 1;
    int wn = warp & 1;
    int grp = lane >> 2;
    int tig = lane & 3;

    int b  = blockIdx.x >> 5;
    int p0 = (blockIdx.x & 31) * 128;

    if (tid < 64) { b1s[tid] = b1[tid]; w2s[tid] = w2[tid]; }

    float acc[2][4][4];
#pragma unroll
    for (int mt = 0; mt < 2; mt++)
#pragma unroll
        for (int nt = 0; nt < 4; nt++)
#pragma unroll
            for (int j = 0; j < 4; j++) acc[mt][nt][j] = 0.f;

    for (int c0 = 0; c0 < CC; c0 += 32) {
        __syncthreads();
#pragma unroll
        for (int i = 0; i < 4; i++) {
            int idx = tid + i * 256;
            int cl = idx >> 5, p4 = (idx & 31) * 4;
            float4 v = *(const float4*)(x + (((size_t)(b * CC + c0 + cl)) << 12) + p0 + p4);
            float* d = &u.t.As[cl * 132 + p4];
            d[0] = v.x; d[1] = v.y; d[2] = v.z; d[3] = v.w;
        }
#pragma unroll
        for (int i = 0; i < 2; i++) {
            int idx = tid + i * 256;
            int j = idx >> 3, c4 = (idx & 7) * 4;
            float4 v = *(const float4*)(w1 + j * CC + c0 + c4);
            float* d = &u.t.Ws[j * 36 + c4];
            d[0] = v.x; d[1] = v.y; d[2] = v.z; d[3] = v.w;
        }
        __syncthreads();

#pragma unroll
        for (int kc = 0; kc < 4; kc++) {
            unsigned ah[2][4], al[2][4];
#pragma unroll
            for (int mt = 0; mt < 2; mt++) {
                int row = wm * 32 + mt * 16 + grp;
                int col = kc * 8 + tig;
                tf32_split(u.t.As[col * 132 + row],           ah[mt][0], al[mt][0]);
                tf32_split(u.t.As[col * 132 + row + 8],       ah[mt][1], al[mt][1]);
                tf32_split(u.t.As[(col + 4) * 132 + row],     ah[mt][2], al[mt][2]);
                tf32_split(u.t.As[(col + 4) * 132 + row + 8], ah[mt][3], al[mt][3]);
            }
#pragma unroll
            for (int nt = 0; nt < 4; nt++) {
                int n = wn * 32 + nt * 8 + grp;
                int col = kc * 8 + tig;
                unsigned bh0, bl0, bh1, bl1;
                tf32_split(u.t.Ws[n * 36 + col],     bh0, bl0);
                tf32_split(u.t.Ws[n * 36 + col + 4], bh1, bl1);
#pragma unroll
                for (int mt = 0; mt < 2; mt++) {
                    mma_tf32(acc[mt][nt], ah[mt][0], ah[mt][1], ah[mt][2], ah[mt][3], bh0, bh1);
                    mma_tf32(acc[mt][nt], ah[mt][0], ah[mt][1], ah[mt][2], ah[mt][3], bl0, bl1);
                    mma_tf32(acc[mt][nt], al[mt][0], al[mt][1], al[mt][2], al[mt][3], bh0, bh1);
                }
            }
        }
    }
    __syncthreads();

    // epilogue: bias + exact GELU into smem
#pragma unroll
    for (int mt = 0; mt < 2; mt++) {
#pragma unroll
        for (int nt = 0; nt < 4; nt++) {
#pragma unroll
            for (int j = 0; j < 4; j++) {
                int row = wm * 32 + mt * 16 + grp + ((j >= 2) ? 8 : 0);
                int col = wn * 32 + nt * 8 + tig * 2 + (j & 1);
                float v = acc[mt][nt][j] + b1s[col];
                u.Hs[row * 65 + col] = 0.5f * v * (1.0f + erff(v * 0.70710678118654752f));
            }
        }
    }
    __syncthreads();

    int row = tid >> 1;
    int jh  = (tid & 1) * 32;
    float s = 0.f;
#pragma unroll
    for (int jj = 0; jj < 32; jj++) s += u.Hs[row * 65 + jh + jj] * w2s[jh + jj];
    s += __shfl_xor_sync(0xffffffff, s, 1);
    if ((tid & 1) == 0) {
        float acc2 = s + b2[0];
        float sg  = 1.0f / (1.0f + __expf(-acc2));
        float val = sg + 0.5f * bmap[(b << 12) + p0 + row];
        imp[(b << 12) + p0 + row] = val;
        if (imp_out) imp_out[(b << 12) + p0 + row] = val;
    }
}

// ---------------- kernel 2: exact top-K via bitonic sort ----------------
__global__ void topk_kernel(const float* __restrict__ imp,
                            int* __restrict__ topidx,
                            int* __restrict__ pos2k)
{
    __shared__ unsigned long long keys[NN];
    __shared__ int idxs[KK];
    int tid = threadIdx.x;  // 1024
    int b = blockIdx.x;

    for (int i = tid; i < NN; i += 1024) {
        unsigned int fb = __float_as_uint(imp[(b << 12) + i]);
        keys[i] = ((unsigned long long)fb << 32) | (unsigned int)(NN - 1 - i);
        pos2k[(b << 12) + i] = -1;
    }
    __syncthreads();

    for (int k2 = 2; k2 <= NN; k2 <<= 1) {
        for (int j = k2 >> 1; j > 0; j >>= 1) {
            for (int t = tid; t < NN; t += 1024) {
                int ixj = t ^ j;
                if (ixj > t) {
                    unsigned long long a = keys[t], c = keys[ixj];
                    if ((a < c) == ((t & k2) == 0)) { keys[t] = c; keys[ixj] = a; }
                }
            }
            __syncthreads();
        }
    }
    idxs[tid] = (NN - 1) - (int)(keys[tid] & 0xFFFFFFFFull);
    __syncthreads();
    for (int k2 = 2; k2 <= KK; k2 <<= 1) {
        for (int j = k2 >> 1; j > 0; j >>= 1) {
            int ixj = tid ^ j;
            if (ixj > tid) {
                int a = idxs[tid], c = idxs[ixj];
                if ((a > c) == ((tid & k2) == 0)) { idxs[tid] = c; idxs[ixj] = a; }
            }
            __syncthreads();
        }
    }
    int p = idxs[tid];
    topidx[(b << 10) + tid] = p;
    pos2k[(b << 12) + p] = tid;
}

// ---------------- kernel 3: gather via smem transpose ----------------
__global__ void gather_kernel(const float* __restrict__ x,
                              const int* __restrict__ topidx,
                              float* __restrict__ xsp)
{
    __shared__ float sm[32][33];
    int k0 = blockIdx.x * 32;
    int c0 = blockIdx.y * 32;
    int b  = blockIdx.z;
    int tid = threadIdx.x;
    int l = tid & 31, g = tid >> 5;

    int p = topidx[(b << 10) + k0 + l];
#pragma unroll
    for (int r = 0; r < 4; r++) {
        int cl = g + r * 8;
        sm[cl][l] = x[(((size_t)(b * CC + c0 + cl)) << 12) + p];
    }
    __syncthreads();
#pragma unroll
    for (int r = 0; r < 4; r++) {
        int kl = g + r * 8;
        xsp[(((size_t)((b << 10) + k0 + kl)) << 8) + c0 + l] = sm[l][kl];
    }
}

// ---------------- kernel 4: 2-term tf32 GEMM (R9 form; no prefetch; 3 CTAs/SM) ----------------
__global__ void __launch_bounds__(256, 3)
gemm_tf32_kernel(const float* __restrict__ A,
                 const float* __restrict__ W0, const float* __restrict__ B0, float* __restrict__ C0,
                 const float* __restrict__ W1, const float* __restrict__ B1, float* __restrict__ C1,
                 const float* __restrict__ W2, const float* __restrict__ B2, float* __restrict__ C2,
                 int M, int Nn, int Kd)
{
    const float* W    = W0;
    const float* bias = B0;
    float*       Cout = C0;
    if (blockIdx.z == 1)      { W = W1; bias = B1; Cout = C1; }
    else if (blockIdx.z == 2) { W = W2; bias = B2; Cout = C2; }

    __shared__ float As[128 * 36];
    __shared__ float Ws[64 * 36];

    int tid  = threadIdx.x;
    int lane = tid & 31;
    int warp = tid >> 5;
    int wm = warp >> 1;
    int wn = warp & 1;
    int grp = lane >> 2;
    int tig = lane & 3;

    int bm = blockIdx.y * 128;
    int bn = blockIdx.x * 64;

    float acc[2][4][4];
#pragma unroll
    for (int mt = 0; mt < 2; mt++)
#pragma unroll
        for (int nt = 0; nt < 4; nt++)
#pragma unroll
            for (int j = 0; j < 4; j++) acc[mt][nt][j] = 0.f;

    for (int c0 = 0; c0 < Kd; c0 += 32) {
        if (c0) __syncthreads();   // WAR: previous chunk's readers done
        // A tile (truncated at store)
#pragma unroll
        for (int i = 0; i < 4; i++) {
            int idx = tid + i * 256;
            int r = idx >> 3, c4 = (idx & 7) * 4;
            float4 v = *(const float4*)(A + (size_t)(bm + r) * Kd + c0 + c4);
            float* d = &As[r * 36 + c4];
            d[0] = tf32_hi_f(v.x); d[1] = tf32_hi_f(v.y);
            d[2] = tf32_hi_f(v.z); d[3] = tf32_hi_f(v.w);
        }
        // W tile (full precision; split at read)
#pragma unroll
        for (int i = 0; i < 2; i++) {
            int idx = tid + i * 256;
            int r = idx >> 3, c4 = (idx & 7) * 4;
            float4 v = *(const float4*)(W + (size_t)(bn + r) * Kd + c0 + c4);
            float* d = &Ws[r * 36 + c4];
            d[0] = v.x; d[1] = v.y; d[2] = v.z; d[3] = v.w;
        }
        __syncthreads();

#pragma unroll
        for (int kc = 0; kc < 4; kc++) {
            unsigned ah[2][4];
#pragma unroll
            for (int mt = 0; mt < 2; mt++) {
                int row = wm * 32 + mt * 16 + grp;
                int col = kc * 8 + tig;
                ah[mt][0] = __float_as_uint(As[row * 36 + col]);
                ah[mt][1] = __float_as_uint(As[(row + 8) * 36 + col]);
                ah[mt][2] = __float_as_uint(As[row * 36 + col + 4]);
                ah[mt][3] = __float_as_uint(As[(row + 8) * 36 + col + 4]);
            }
#pragma unroll
            for (int nt = 0; nt < 4; nt++) {
                int n = wn * 32 + nt * 8 + grp;
                int col = kc * 8 + tig;
                unsigned bh0, bl0, bh1, bl1;
                tf32_split(Ws[n * 36 + col],     bh0, bl0);
                tf32_split(Ws[n * 36 + col + 4], bh1, bl1);
#pragma unroll
                for (int mt = 0; mt < 2; mt++) {
                    mma_tf32(acc[mt][nt], ah[mt][0], ah[mt][1], ah[mt][2], ah[mt][3], bh0, bh1);
                    mma_tf32(acc[mt][nt], ah[mt][0], ah[mt][1], ah[mt][2], ah[mt][3], bl0, bl1);
                }
            }
        }
    }

#pragma unroll
    for (int mt = 0; mt < 2; mt++) {
#pragma unroll
        for (int nt = 0; nt < 4; nt++) {
            int row = bm + wm * 32 + mt * 16 + grp;
            int col = bn + wn * 32 + nt * 8 + tig * 2;
            float2 bv = *(const float2*)(bias + col);
            float2 v0 = { acc[mt][nt][0] + bv.x, acc[mt][nt][1] + bv.y };
            float2 v1 = { acc[mt][nt][2] + bv.x, acc[mt][nt][3] + bv.y };
            *(float2*)(Cout + (size_t)row * Nn + col)       = v0;
            *(float2*)(Cout + (size_t)(row + 8) * Nn + col) = v1;
        }
    }
}

// ---------------- kernel 5: flash attention, bf16 m16n8k16 ----------------
// Q/K/P/V in bf16 (softmax statistics in fp32). Per warp per 64-key tile:
// QK = 16 MMAs, PV = 16 MMAs. K/V register prefetch as in R10.
// Smem layouts (32-bit words): Kbf rows stride 20, Vp (key-pair packed) stride 40,
// Pp stride 36 — all chosen conflict-free for the fragment access patterns.
__global__ void __launch_bounds__(128, 5)
attn_bf16_kernel(const float* __restrict__ Q,
                 const float* __restrict__ Kb,
                 const float* __restrict__ Vb,
                 float* __restrict__ O)
{
    __shared__ unsigned Kbf[64 * 20];   // [key][dim-pair], 16 pairs used
    __shared__ unsigned Vp [32 * 40];   // [key-pair][dim], packed {V[2j][d], V[2j+1][d]}
    __shared__ unsigned Pp [64 * 36];   // [query][key-pair]; also Q staging (stride 20)

    int tid  = threadIdx.x;   // 128
    int lane = tid & 31;
    int warp = tid >> 5;
    int grp = lane >> 2;
    int tig = lane & 3;
    int wr = warp * 16;

    int m0 = blockIdx.x * 64;
    int hh = blockIdx.y;
    int b  = blockIdx.z;
    size_t base = (size_t)b * KK * CC + hh * HD;
    const float scale = 0.17677669529663687f;  // 1/sqrt(32)

    // stage Q (scaled, bf16-packed) into Pp area, stride 20 words
#pragma unroll
    for (int i = 0; i < 4; i++) {
        int idx = tid + i * 128;
        int r = idx >> 3, c4 = (idx & 7) * 4;
        float4 v = *(const float4*)(Q + base + (size_t)(m0 + r) * CC + c4);
        Pp[r * 20 + (c4 >> 1)    ] = pack_bf16x2(v.x * scale, v.y * scale);
        Pp[r * 20 + (c4 >> 1) + 1] = pack_bf16x2(v.z * scale, v.w * scale);
    }
    __syncthreads();

    unsigned qf[2][4];
#pragma unroll
    for (int kc = 0; kc < 2; kc++) {
        int cp = kc * 8 + tig;
        qf[kc][0] = Pp[(wr + grp) * 20 + cp];
        qf[kc][1] = Pp[(wr + grp + 8) * 20 + cp];
        qf[kc][2] = Pp[(wr + grp) * 20 + cp + 4];
        qf[kc][3] = Pp[(wr + grp + 8) * 20 + cp + 4];
    }
    __syncthreads();

    float mr0 = -INFINITY, mr1 = -INFINITY, l0 = 0.f, l1 = 0.f;
    float oacc[4][4];
#pragma unroll
    for (int dt = 0; dt < 4; dt++)
#pragma unroll
        for (int j = 0; j < 4; j++) oacc[dt][j] = 0.f;

    // prologue: tile 0 into registers
    float4 rk[4];                 // K rows:   idx -> (r = idx>>3, c4)
    float4 rv0[2], rv1[2];        // V pairs:  idx -> (j = idx>>3, c4); rows 2j, 2j+1
#pragma unroll
    for (int i = 0; i < 4; i++) {
        int idx = tid + i * 128;
        int r = idx >> 3, c4 = (idx & 7) * 4;
        rk[i] = *(const float4*)(Kb + base + (size_t)r * CC + c4);
    }
#pragma unroll
    for (int i = 0; i < 2; i++) {
        int idx = tid + i * 128;
        int j = idx >> 3, c4 = (idx & 7) * 4;
        rv0[i] = *(const float4*)(Vb + base + (size_t)(2 * j)     * CC + c4);
        rv1[i] = *(const float4*)(Vb + base + (size_t)(2 * j + 1) * CC + c4);
    }

    for (int n0 = 0; n0 < KK; n0 += 64) {
        __syncthreads();
        // commit K (bf16 dim-pairs) and V (bf16 key-pair packed)
#pragma unroll
        for (int i = 0; i < 4; i++) {
            int idx = tid + i * 128;
            int r = idx >> 3, c4 = (idx & 7) * 4;
            Kbf[r * 20 + (c4 >> 1)    ] = pack_bf16x2(rk[i].x, rk[i].y);
            Kbf[r * 20 + (c4 >> 1) + 1] = pack_bf16x2(rk[i].z, rk[i].w);
        }
#pragma unroll
        for (int i = 0; i < 2; i++) {
            int idx = tid + i * 128;
            int j = idx >> 3, c4 = (idx & 7) * 4;
            unsigned* d = &Vp[j * 40 + c4];
            d[0] = pack_bf16x2(rv0[i].x, rv1[i].x);
            d[1] = pack_bf16x2(rv0[i].y, rv1[i].y);
            d[2] = pack_bf16x2(rv0[i].z, rv1[i].z);
            d[3] = pack_bf16x2(rv0[i].w, rv1[i].w);
        }
        __syncthreads();

        // prefetch next tile
        if (n0 + 64 < KK) {
#pragma unroll
            for (int i = 0; i < 4; i++) {
                int idx = tid + i * 128;
                int r = idx >> 3, c4 = (idx & 7) * 4;
                rk[i] = *(const float4*)(Kb + base + (size_t)(n0 + 64 + r) * CC + c4);
            }
#pragma unroll
            for (int i = 0; i < 2; i++) {
                int idx = tid + i * 128;
                int j = idx >> 3, c4 = (idx & 7) * 4;
                rv0[i] = *(const float4*)(Vb + base + (size_t)(n0 + 64 + 2 * j)     * CC + c4);
                rv1[i] = *(const float4*)(Vb + base + (size_t)(n0 + 64 + 2 * j + 1) * CC + c4);
            }
        }

        // S = Q K^T  (bf16, 2 kc x 8 nt MMAs)
        float s[8][4];
#pragma unroll
        for (int nt = 0; nt < 8; nt++) {
            s[nt][0] = s[nt][1] = s[nt][2] = s[nt][3] = 0.f;
        }
#pragma unroll
        for (int kc = 0; kc < 2; kc++) {
#pragma unroll
            for (int nt = 0; nt < 8; nt++) {
                int n = nt * 8 + grp;
                unsigned b0 = Kbf[n * 20 + kc * 8 + tig];
                unsigned b1 = Kbf[n * 20 + kc * 8 + tig + 4];
                mma_bf16(s[nt], qf[kc][0], qf[kc][1], qf[kc][2], qf[kc][3], b0, b1);
            }
        }

        // online softmax (rows wr+grp and wr+grp+8)
        float tm0 = -INFINITY, tm1 = -INFINITY;
#pragma unroll
        for (int nt = 0; nt < 8; nt++) {
            tm0 = fmaxf(tm0, fmaxf(s[nt][0], s[nt][1]));
            tm1 = fmaxf(tm1, fmaxf(s[nt][2], s[nt][3]));
        }
        tm0 = fmaxf(tm0, __shfl_xor_sync(0xffffffff, tm0, 1));
        tm0 = fmaxf(tm0, __shfl_xor_sync(0xffffffff, tm0, 2));
        tm1 = fmaxf(tm1, __shfl_xor_sync(0xffffffff, tm1, 1));
        tm1 = fmaxf(tm1, __shfl_xor_sync(0xffffffff, tm1, 2));

        float mn0 = fmaxf(mr0, tm0), mn1 = fmaxf(mr1, tm1);
        float corr0 = __expf(mr0 - mn0), corr1 = __expf(mr1 - mn1);
        float ps0 = 0.f, ps1 = 0.f;
#pragma unroll
        for (int nt = 0; nt < 8; nt++) {
            float p0 = __expf(s[nt][0] - mn0);
            float p1 = __expf(s[nt][1] - mn0);
            float p2 = __expf(s[nt][2] - mn1);
            float p3 = __expf(s[nt][3] - mn1);
            ps0 += p0 + p1; ps1 += p2 + p3;       // l-sum in full fp32
            int cp = nt * 4 + tig;                 // key-pair column
            Pp[(wr + grp) * 36 + cp]     = pack_bf16x2(p0, p1);
            Pp[(wr + grp + 8) * 36 + cp] = pack_bf16x2(p2, p3);
        }
        ps0 += __shfl_xor_sync(0xffffffff, ps0, 1);
        ps0 += __shfl_xor_sync(0xffffffff, ps0, 2);
        ps1 += __shfl_xor_sync(0xffffffff, ps1, 1);
        ps1 += __shfl_xor_sync(0xffffffff, ps1, 2);
        l0 = l0 * corr0 + ps0;
        l1 = l1 * corr1 + ps1;
#pragma unroll
        for (int dt = 0; dt < 4; dt++) {
            oacc[dt][0] *= corr0; oacc[dt][1] *= corr0;
            oacc[dt][2] *= corr1; oacc[dt][3] *= corr1;
        }
        mr0 = mn0; mr1 = mn1;
        __syncwarp();

        // O += P V  (bf16, 4 kc x 4 dt MMAs)
#pragma unroll
        for (int kc = 0; kc < 4; kc++) {
            unsigned a0 = Pp[(wr + grp) * 36 + kc * 8 + tig];
            unsigned a1 = Pp[(wr + grp + 8) * 36 + kc * 8 + tig];
            unsigned a2 = Pp[(wr + grp) * 36 + kc * 8 + tig + 4];
            unsigned a3 = Pp[(wr + grp + 8) * 36 + kc * 8 + tig + 4];
#pragma unroll
            for (int dt = 0; dt < 4; dt++) {
                unsigned b0 = Vp[(kc * 8 + tig) * 40 + dt * 8 + grp];
                unsigned b1 = Vp[(kc * 8 + tig + 4) * 40 + dt * 8 + grp];
                mma_bf16(oacc[dt], a0, a1, a2, a3, b0, b1);
            }
        }
        __syncwarp();
    }

    float inv0 = 1.0f / l0, inv1 = 1.0f / l1;
    int row = m0 + wr + grp;
#pragma unroll
    for (int dt = 0; dt < 4; dt++) {
        int col = dt * 8 + tig * 2;
        float2 v0 = { oacc[dt][0] * inv0, oacc[dt][1] * inv0 };
        float2 v1 = { oacc[dt][2] * inv1, oacc[dt][3] * inv1 };
        *(float2*)(O + base + (size_t)row * CC + col)       = v0;
        *(float2*)(O + base + (size_t)(row + 8) * CC + col) = v1;
    }
}

// ---------------- kernel 6: residual + LayerNorm ----------------
__global__ void ln_kernel(const float* __restrict__ P,
                          const float* __restrict__ X,
                          const float* __restrict__ g,
                          const float* __restrict__ beta,
                          float* __restrict__ E)
{
    int row = blockIdx.x;
    int c = threadIdx.x;
    size_t off = (size_t)row * CC + c;
    float y = P[off] + X[off];
    float v1 = y, v2 = y * y;
#pragma unroll
    for (int o = 16; o > 0; o >>= 1) {
        v1 += __shfl_xor_sync(0xffffffff, v1, o);
        v2 += __shfl_xor_sync(0xffffffff, v2, o);
    }
    __shared__ float s1[8], s2[8];
    int w = c >> 5, ln = c & 31;
    if (ln == 0) { s1[w] = v1; s2[w] = v2; }
    __syncthreads();
    float sum = 0.f, sq = 0.f;
#pragma unroll
    for (int i = 0; i < 8; i++) { sum += s1[i]; sq += s2[i]; }
    float mu  = sum * (1.0f / CC);
    float var = sq * (1.0f / CC) - mu * mu;
    float rs  = rsqrtf(var + 1e-5f);
    E[off] = (y - mu) * rs * g[c] + beta[c];
}

// ---------------- kernel 7: copy x -> out, overlay enhanced tokens ----------------
__global__ void scatter_kernel(const float* __restrict__ X,
                               const int* __restrict__ pos2k,
                               const float* __restrict__ E,
                               float* __restrict__ out)
{
    int gid = blockIdx.x * 256 + threadIdx.x;
    int b = gid >> 20;
    int c = (gid >> 12) & (CC - 1);
    int p = gid & (NN - 1);
    int k = pos2k[(b << 12) + p];
    float v = (k >= 0) ? E[(size_t)(((b << 10) + k) << 8) + c] : X[gid];
    out[gid] = v;
}

// ---------------- launch ----------------
extern "C" void kernel_launch(void* const* d_in, const int* in_sizes, int n_in,
                              void* d_out, int out_size)
{
    const float* x    = (const float*)d_in[0];
    const float* bmap = (const float*)d_in[1];
    const float* iw1  = (const float*)d_in[2];
    const float* ib1  = (const float*)d_in[3];
    const float* iw2  = (const float*)d_in[4];
    const float* ib2  = (const float*)d_in[5];
    const float* wq   = (const float*)d_in[6];
    const float* bq   = (const float*)d_in[7];
    const float* wk   = (const float*)d_in[8];
    const float* bk   = (const float*)d_in[9];
    const float* wv   = (const float*)d_in[10];
    const float* bv   = (const float*)d_in[11];
    const float* wo   = (const float*)d_in[12];
    const float* bo   = (const float*)d_in[13];
    const float* lng  = (const float*)d_in[14];
    const float* lnb  = (const float*)d_in[15];

    static float *P_imp = nullptr, *P_xsp, *P_q, *P_k, *P_v, *P_ao, *P_ps, *P_enh;
    static int *P_topidx, *P_pos2k;
    if (!P_imp) {
        cudaGetSymbolAddress((void**)&P_imp,    g_imp);
        cudaGetSymbolAddress((void**)&P_topidx, g_topidx);
        cudaGetSymbolAddress((void**)&P_pos2k,  g_pos2k);
        cudaGetSymbolAddress((void**)&P_xsp,    g_xsp);
        cudaGetSymbolAddress((void**)&P_q,      g_q);
        cudaGetSymbolAddress((void**)&P_k,      g_k);
        cudaGetSymbolAddress((void**)&P_v,      g_v);
        cudaGetSymbolAddress((void**)&P_ao,     g_ao);
        cudaGetSymbolAddress((void**)&P_ps,     g_ps);
        cudaGetSymbolAddress((void**)&P_enh,    g_enh);
    }

    float* out = (float*)d_out;
    float* imp_out = (out_size >= BB * CC * NN + BB * NN) ? out + (size_t)BB * CC * NN
                                                          : nullptr;

    importance_mma_kernel<<<BB * 32, 256>>>(x, bmap, iw1, ib1, iw2, ib2,
                                            P_imp, imp_out);
    topk_kernel<<<BB, 1024>>>(P_imp, P_topidx, P_pos2k);

    dim3 ggrid_gather(KK / 32, CC / 32, BB);
    gather_kernel<<<ggrid_gather, 256>>>(x, P_topidx, P_xsp);

    // fused QKV projections (grid.z selects weight set)
    dim3 ggrid3(CC / 64, (BB * KK) / 128, 3);
    gemm_tf32_kernel<<<ggrid3, 256>>>(P_xsp,
                                      wq, bq, P_q,
                                      wk, bk, P_k,
                                      wv, bv, P_v,
                                      BB * KK, CC, CC);

    dim3 agrid(KK / 64, NH, BB);
    attn_bf16_kernel<<<agrid, 128>>>(P_q, P_k, P_v, P_ao);

    dim3 ggrid1(CC / 64, (BB * KK) / 128, 1);
    gemm_tf32_kernel<<<ggrid1, 256>>>(P_ao,
                                      wo, bo, P_ps,
                                      wo, bo, P_ps,
                                      wo, bo, P_ps,
                                      BB * KK, CC, CC);

    ln_kernel<<<BB * KK, 256>>>(P_ps, P_xsp, lng, lnb, P_enh);
    scatter_kernel<<<(BB * CC * NN) / 256, 256>>>(x, P_pos2k, P_enh, out);
}

// round 14
// speedup vs baseline: 2.7923x; 1.1043x over previous
#include <cuda_runtime.h>
#include <cuda_fp16.h>
#include <math.h>

// ===== problem constants (DSA_5866925326622) =====
#define BB   8
#define CC   256
#define NN   4096
#define KK   1024
#define NH   8
#define HD   32
#define CH   64

// ===== persistent scratch (device globals; allocation-free) =====
__device__ float g_imp  [BB * NN];
__device__ int   g_topidx[BB * KK];
__device__ int   g_pos2k [BB * NN];
__device__ float g_xsp  [BB * KK * CC];
__device__ float g_q    [BB * KK * CC];
__device__ float g_k    [BB * KK * CC];
__device__ float g_v    [BB * KK * CC];
__device__ float g_ao   [BB * KK * CC];
__device__ float g_ps   [BB * KK * CC];
__device__ float g_enh  [BB * KK * CC];

// ===== mma wrappers =====
__device__ __forceinline__ void mma_tf32(float* d,
                                         unsigned a0, unsigned a1, unsigned a2, unsigned a3,
                                         unsigned b0, unsigned b1)
{
    asm volatile(
        "mma.sync.aligned.m16n8k8.row.col.f32.tf32.tf32.f32 "
        "{%0,%1,%2,%3}, {%4,%5,%6,%7}, {%8,%9}, {%0,%1,%2,%3};\n"
        : "+f"(d[0]), "+f"(d[1]), "+f"(d[2]), "+f"(d[3])
        : "r"(a0), "r"(a1), "r"(a2), "r"(a3), "r"(b0), "r"(b1));
}

__device__ __forceinline__ void mma_bf16(float* d,
                                         unsigned a0, unsigned a1, unsigned a2, unsigned a3,
                                         unsigned b0, unsigned b1)
{
    asm volatile(
        "mma.sync.aligned.m16n8k16.row.col.f32.bf16.bf16.f32 "
        "{%0,%1,%2,%3}, {%4,%5,%6,%7}, {%8,%9}, {%0,%1,%2,%3};\n"
        : "+f"(d[0]), "+f"(d[1]), "+f"(d[2]), "+f"(d[3])
        : "r"(a0), "r"(a1), "r"(a2), "r"(a3), "r"(b0), "r"(b1));
}

__device__ __forceinline__ void mma_f16(float* d,
                                        unsigned a0, unsigned a1, unsigned a2, unsigned a3,
                                        unsigned b0, unsigned b1)
{
    asm volatile(
        "mma.sync.aligned.m16n8k16.row.col.f32.f16.f16.f32 "
        "{%0,%1,%2,%3}, {%4,%5,%6,%7}, {%8,%9}, {%0,%1,%2,%3};\n"
        : "+f"(d[0]), "+f"(d[1]), "+f"(d[2]), "+f"(d[3])
        : "r"(a0), "r"(a1), "r"(a2), "r"(a3), "r"(b0), "r"(b1));
}

// exact split into two tf32-representable parts
__device__ __forceinline__ void tf32_split(float x, unsigned& hi, unsigned& lo)
{
    unsigned h = __float_as_uint(x) & 0xFFFFE000u;
    hi = h;
    lo = __float_as_uint(x - __uint_as_float(h));
}

// word.lo = first arg (even-k element), word.hi = second arg (odd-k element)
__device__ __forceinline__ unsigned pack_bf16x2(float e, float o)
{
    unsigned r;
    asm("cvt.rn.bf16x2.f32 %0, %1, %2;" : "=r"(r) : "f"(o), "f"(e));
    return r;
}

__device__ __forceinline__ unsigned pack_f16x2(float e, float o)
{
    unsigned r;
    asm("cvt.rn.f16x2.f32 %0, %1, %2;" : "=r"(r) : "f"(o), "f"(e));
    return r;
}

__device__ __forceinline__ float f16_rn_f(float x)
{
    return __half2float(__float2half_rn(x));
}

// ===== kernel 1: importance net, 3-term tf32 split (fp32-exact; feeds top-K) =====
__global__ void importance_mma_kernel(const float* __restrict__ x,
                                      const float* __restrict__ bmap,
                                      const float* __restrict__ w1,
                                      const float* __restrict__ b1,
                                      const float* __restrict__ w2,
                                      const float* __restrict__ b2,
                                      float* __restrict__ imp,
                                      float* __restrict__ imp_out)
{
    __shared__ union {
        struct { float As[32 * 132]; float Ws[64 * 36]; } t;
        float Hs[128 * 65];
    } u;
    __shared__ float b1s[64], w2s[64];

    const int tid  = threadIdx.x;   // 256
    const int lane = tid & 31;
    const int warp = tid >> 5;
    const int wm = warp >> 1, wn = warp & 1;
    const int grp = lane >> 2, tig = lane & 3;

    const int b  = blockIdx.x >> 5;
    const int p0 = (blockIdx.x & 31) * 128;

    if (tid < 64) { b1s[tid] = b1[tid]; w2s[tid] = w2[tid]; }

    float acc[2][4][4];
#pragma unroll
    for (int mt = 0; mt < 2; mt++)
#pragma unroll
        for (int nt = 0; nt < 4; nt++)
#pragma unroll
            for (int j = 0; j < 4; j++) acc[mt][nt][j] = 0.f;

    for (int c0 = 0; c0 < CC; c0 += 32) {
        __syncthreads();
#pragma unroll
        for (int i = 0; i < 4; i++) {
            int idx = tid + i * 256;
            int cl = idx >> 5, p4 = (idx & 31) * 4;
            float4 v = *(const float4*)(x + (((size_t)(b * CC + c0 + cl)) << 12) + p0 + p4);
            float* d = &u.t.As[cl * 132 + p4];
            d[0] = v.x; d[1] = v.y; d[2] = v.z; d[3] = v.w;
        }
#pragma unroll
        for (int i = 0; i < 2; i++) {
            int idx = tid + i * 256;
            int j = idx >> 3, c4 = (idx & 7) * 4;
            float4 v = *(const float4*)(w1 + j * CC + c0 + c4);
            float* d = &u.t.Ws[j * 36 + c4];
            d[0] = v.x; d[1] = v.y; d[2] = v.z; d[3] = v.w;
        }
        __syncthreads();

#pragma unroll
        for (int kc = 0; kc < 4; kc++) {
            unsigned ah[2][4], al[2][4];
#pragma unroll
            for (int mt = 0; mt < 2; mt++) {
                int row = wm * 32 + mt * 16 + grp;
                int col = kc * 8 + tig;
                tf32_split(u.t.As[col * 132 + row],           ah[mt][0], al[mt][0]);
                tf32_split(u.t.As[col * 132 + row + 8],       ah[mt][1], al[mt][1]);
                tf32_split(u.t.As[(col + 4) * 132 + row],     ah[mt][2], al[mt][2]);
                tf32_split(u.t.As[(col + 4) * 132 + row + 8], ah[mt][3], al[mt][3]);
            }
#pragma unroll
            for (int nt = 0; nt < 4; nt++) {
                int n = wn * 32 + nt * 8 + grp;
                int col = kc * 8 + tig;
                unsigned bh0, bl0, bh1, bl1;
                tf32_split(u.t.Ws[n * 36 + col],     bh0, bl0);
                tf32_split(u.t.Ws[n * 36 + col + 4], bh1, bl1);
#pragma unroll
                for (int mt = 0; mt < 2; mt++) {
                    mma_tf32(acc[mt][nt], ah[mt][0], ah[mt][1], ah[mt][2], ah[mt][3], bh0, bh1);
                    mma_tf32(acc[mt][nt], ah[mt][0], ah[mt][1], ah[mt][2], ah[mt][3], bl0, bl1);
                    mma_tf32(acc[mt][nt], al[mt][0], al[mt][1], al[mt][2], al[mt][3], bh0, bh1);
                }
            }
        }
    }
    __syncthreads();

#pragma unroll
    for (int mt = 0; mt < 2; mt++) {
#pragma unroll
        for (int nt = 0; nt < 4; nt++) {
#pragma unroll
            for (int j = 0; j < 4; j++) {
                int row = wm * 32 + mt * 16 + grp + ((j >= 2) ? 8 : 0);
                int col = wn * 32 + nt * 8 + tig * 2 + (j & 1);
                float v = acc[mt][nt][j] + b1s[col];
                u.Hs[row * 65 + col] = 0.5f * v * (1.0f + erff(v * 0.70710678118654752f));
            }
        }
    }
    __syncthreads();

    const int row = tid >> 1;
    const int jh  = (tid & 1) * 32;
    float s = 0.f;
#pragma unroll
    for (int jj = 0; jj < 32; jj++) s += u.Hs[row * 65 + jh + jj] * w2s[jh + jj];
    s += __shfl_xor_sync(0xffffffff, s, 1);
    if ((tid & 1) == 0) {
        float z  = s + b2[0];
        float sg = 1.0f / (1.0f + __expf(-z));
        float val = sg + 0.5f * bmap[(b << 12) + p0 + row];
        imp[(b << 12) + p0 + row] = val;
        if (imp_out) imp_out[(b << 12) + p0 + row] = val;
    }
}

// ===== kernel 2: exact top-K, bitonic (jax tie-break order) =====
__global__ void topk_kernel(const float* __restrict__ imp,
                            int* __restrict__ topidx,
                            int* __restrict__ pos2k)
{
    __shared__ unsigned long long keys[NN];
    __shared__ int idxs[KK];
    const int tid = threadIdx.x;  // 1024
    const int b = blockIdx.x;

    for (int i = tid; i < NN; i += 1024) {
        unsigned fb = __float_as_uint(imp[(b << 12) + i]);
        keys[i] = ((unsigned long long)fb << 32) | (unsigned)(NN - 1 - i);
        pos2k[(b << 12) + i] = -1;
    }
    __syncthreads();

    for (int k2 = 2; k2 <= NN; k2 <<= 1)
        for (int j = k2 >> 1; j > 0; j >>= 1) {
            for (int t = tid; t < NN; t += 1024) {
                int ixj = t ^ j;
                if (ixj > t) {
                    unsigned long long a = keys[t], c = keys[ixj];
                    if ((a < c) == ((t & k2) == 0)) { keys[t] = c; keys[ixj] = a; }
                }
            }
            __syncthreads();
        }

    idxs[tid] = (NN - 1) - (int)(keys[tid] & 0xFFFFFFFFull);
    __syncthreads();
    for (int k2 = 2; k2 <= KK; k2 <<= 1)
        for (int j = k2 >> 1; j > 0; j >>= 1) {
            int ixj = tid ^ j;
            if (ixj > tid) {
                int a = idxs[tid], c = idxs[ixj];
                if ((a > c) == ((tid & k2) == 0)) { idxs[tid] = c; idxs[ixj] = a; }
            }
            __syncthreads();
        }

    int p = idxs[tid];
    topidx[(b << 10) + tid] = p;
    pos2k[(b << 12) + p] = tid;
}

// ===== kernel 3: gather (smem transpose) =====
__global__ void gather_kernel(const float* __restrict__ x,
                              const int* __restrict__ topidx,
                              float* __restrict__ xsp)
{
    __shared__ float sm[32][33];
    const int k0 = blockIdx.x * 32;
    const int c0 = blockIdx.y * 32;
    const int b  = blockIdx.z;
    const int tid = threadIdx.x;
    const int l = tid & 31, g = tid >> 5;

    int p = topidx[(b << 10) + k0 + l];
#pragma unroll
    for (int r = 0; r < 4; r++) {
        int cl = g + r * 8;
        sm[cl][l] = x[(((size_t)(b * CC + c0 + cl)) << 12) + p];
    }
    __syncthreads();
#pragma unroll
    for (int r = 0; r < 4; r++) {
        int kl = g + r * 8;
        xsp[(((size_t)((b << 10) + k0 + kl)) << 8) + c0 + l] = sm[l][kl];
    }
}

// ===== kernel 4: fp16 2-term GEMM (m16n8k16), double-buffered, 1 sync/chunk =====
// acc += rn16(A) * (Wh + Wl), with W == Wh + Wl exactly (Wl is the fp16 residual).
// Dropped term: (A - rn16(A)) * W, <= 2^-11 relative — same class as 2-term tf32.
__global__ void __launch_bounds__(256, 3)
gemm_f16_kernel(const float* __restrict__ A,
                const float* __restrict__ W0, const float* __restrict__ B0, float* __restrict__ C0,
                const float* __restrict__ W1, const float* __restrict__ B1, float* __restrict__ C1,
                const float* __restrict__ W2, const float* __restrict__ B2, float* __restrict__ C2,
                int M, int Nn, int Kd)
{
    const float* W    = W0;
    const float* bias = B0;
    float*       Cout = C0;
    if (blockIdx.z == 1)      { W = W1; bias = B1; Cout = C1; }
    else if (blockIdx.z == 2) { W = W2; bias = B2; Cout = C2; }

    __shared__ unsigned Ahp[2][128 * 20];
    __shared__ unsigned Whp[2][64 * 20];
    __shared__ unsigned Wlp[2][64 * 20];

    const int tid  = threadIdx.x;
    const int lane = tid & 31;
    const int warp = tid >> 5;
    const int wm = warp >> 1, wn = warp & 1;
    const int grp = lane >> 2, tig = lane & 3;

    const int bm = blockIdx.y * 128;
    const int bn = blockIdx.x * 64;

    float acc[2][4][4];
#pragma unroll
    for (int mt = 0; mt < 2; mt++)
#pragma unroll
        for (int nt = 0; nt < 4; nt++)
#pragma unroll
            for (int j = 0; j < 4; j++) acc[mt][nt][j] = 0.f;

    int buf = 0;
    for (int c0 = 0; c0 < Kd; c0 += 32, buf ^= 1) {
#pragma unroll
        for (int i = 0; i < 4; i++) {
            int idx = tid + i * 256;
            int r = idx >> 3, c4 = (idx & 7) * 4;
            float4 v = *(const float4*)(A + (size_t)(bm + r) * Kd + c0 + c4);
            unsigned* d = &Ahp[buf][r * 20 + (c4 >> 1)];
            d[0] = pack_f16x2(v.x, v.y);
            d[1] = pack_f16x2(v.z, v.w);
        }
#pragma unroll
        for (int i = 0; i < 2; i++) {
            int idx = tid + i * 256;
            int r = idx >> 3, c4 = (idx & 7) * 4;
            float4 v = *(const float4*)(W + (size_t)(bn + r) * Kd + c0 + c4);
            float h0 = f16_rn_f(v.x), h1 = f16_rn_f(v.y);
            float h2 = f16_rn_f(v.z), h3 = f16_rn_f(v.w);
            unsigned* dh = &Whp[buf][r * 20 + (c4 >> 1)];
            unsigned* dl = &Wlp[buf][r * 20 + (c4 >> 1)];
            dh[0] = pack_f16x2(h0, h1);
            dh[1] = pack_f16x2(h2, h3);
            dl[0] = pack_f16x2(v.x - h0, v.y - h1);
            dl[1] = pack_f16x2(v.z - h2, v.w - h3);
        }
        __syncthreads();   // double-buffered: one barrier per chunk is sufficient

#pragma unroll
        for (int kc = 0; kc < 2; kc++) {
            const int cp0 = kc * 8;
            unsigned af[2][4];
#pragma unroll
            for (int mt = 0; mt < 2; mt++) {
                int row = wm * 32 + mt * 16 + grp;
                af[mt][0] = Ahp[buf][row * 20 + cp0 + tig];
                af[mt][1] = Ahp[buf][(row + 8) * 20 + cp0 + tig];
                af[mt][2] = Ahp[buf][row * 20 + cp0 + tig + 4];
                af[mt][3] = Ahp[buf][(row + 8) * 20 + cp0 + tig + 4];
            }
#pragma unroll
            for (int nt = 0; nt < 4; nt++) {
                int n = wn * 32 + nt * 8 + grp;
                unsigned wh0 = Whp[buf][n * 20 + cp0 + tig];
                unsigned wh1 = Whp[buf][n * 20 + cp0 + tig + 4];
                unsigned wl0 = Wlp[buf][n * 20 + cp0 + tig];
                unsigned wl1 = Wlp[buf][n * 20 + cp0 + tig + 4];
#pragma unroll
                for (int mt = 0; mt < 2; mt++) {
                    mma_f16(acc[mt][nt], af[mt][0], af[mt][1], af[mt][2], af[mt][3], wh0, wh1);
                    mma_f16(acc[mt][nt], af[mt][0], af[mt][1], af[mt][2], af[mt][3], wl0, wl1);
                }
            }
        }
    }

#pragma unroll
    for (int mt = 0; mt < 2; mt++) {
#pragma unroll
        for (int nt = 0; nt < 4; nt++) {
            int row = bm + wm * 32 + mt * 16 + grp;
            int col = bn + wn * 32 + nt * 8 + tig * 2;
            float2 bv = *(const float2*)(bias + col);
            float2 o0 = { acc[mt][nt][0] + bv.x, acc[mt][nt][1] + bv.y };
            float2 o1 = { acc[mt][nt][2] + bv.x, acc[mt][nt][3] + bv.y };
            *(float2*)(Cout + (size_t)row * Nn + col)       = o0;
            *(float2*)(Cout + (size_t)(row + 8) * Nn + col) = o1;
        }
    }
}

// ===== kernel 5: flash attention (bf16 MMA, double-buffered K/V, fp32 softmax) =====
__global__ void __launch_bounds__(128, 5)
attn_bf16_kernel(const float* __restrict__ Q,
                 const float* __restrict__ Kb,
                 const float* __restrict__ Vb,
                 float* __restrict__ O)
{
    __shared__ unsigned Kbf[2][64 * 20];
    __shared__ unsigned Vp [2][32 * 40];
    __shared__ unsigned Pp [64 * 36];      // P buffer; also Q staging at stride 20

    const int tid  = threadIdx.x;   // 128
    const int lane = tid & 31;
    const int warp = tid >> 5;
    const int grp = lane >> 2, tig = lane & 3;
    const int wr = warp * 16;

    const int m0 = blockIdx.x * 64;
    const int hh = blockIdx.y;
    const int b  = blockIdx.z;
    const size_t base = (size_t)b * KK * CC + hh * HD;
    const float scale = 0.17677669529663687f;

#pragma unroll
    for (int i = 0; i < 4; i++) {
        int idx = tid + i * 128;
        int r = idx >> 3, c4 = (idx & 7) * 4;
        float4 v = *(const float4*)(Q + base + (size_t)(m0 + r) * CC + c4);
        unsigned* d = &Pp[r * 20 + (c4 >> 1)];
        d[0] = pack_bf16x2(v.x * scale, v.y * scale);
        d[1] = pack_bf16x2(v.z * scale, v.w * scale);
    }
    __syncthreads();

    unsigned qf[2][4];
#pragma unroll
    for (int kc = 0; kc < 2; kc++) {
        int cp = kc * 8 + tig;
        qf[kc][0] = Pp[(wr + grp) * 20 + cp];
        qf[kc][1] = Pp[(wr + grp + 8) * 20 + cp];
        qf[kc][2] = Pp[(wr + grp) * 20 + cp + 4];
        qf[kc][3] = Pp[(wr + grp + 8) * 20 + cp + 4];
    }
    __syncthreads();

    float mr0 = -INFINITY, mr1 = -INFINITY, l0 = 0.f, l1 = 0.f;
    float oacc[4][4];
#pragma unroll
    for (int dt = 0; dt < 4; dt++)
#pragma unroll
        for (int j = 0; j < 4; j++) oacc[dt][j] = 0.f;

    float4 rk[4], rv0[2], rv1[2];
#pragma unroll
    for (int i = 0; i < 4; i++) {
        int idx = tid + i * 128;
        int r = idx >> 3, c4 = (idx & 7) * 4;
        rk[i] = *(const float4*)(Kb + base + (size_t)r * CC + c4);
    }
#pragma unroll
    for (int i = 0; i < 2; i++) {
        int idx = tid + i * 128;
        int j = idx >> 3, c4 = (idx & 7) * 4;
        rv0[i] = *(const float4*)(Vb + base + (size_t)(2 * j)     * CC + c4);
        rv1[i] = *(const float4*)(Vb + base + (size_t)(2 * j + 1) * CC + c4);
    }

    int buf = 0;
    for (int n0 = 0; n0 < KK; n0 += 64, buf ^= 1) {
        // commit tile into buf; double-buffered so a single barrier suffices:
        // writers of buf at iter i+2 already passed barrier i+1, which readers
        // of buf (iter i) only reached after finishing their reads.
#pragma unroll
        for (int i = 0; i < 4; i++) {
            int idx = tid + i * 128;
            int r = idx >> 3, c4 = (idx & 7) * 4;
            unsigned* d = &Kbf[buf][r * 20 + (c4 >> 1)];
            d[0] = pack_bf16x2(rk[i].x, rk[i].y);
            d[1] = pack_bf16x2(rk[i].z, rk[i].w);
        }
#pragma unroll
        for (int i = 0; i < 2; i++) {
            int idx = tid + i * 128;
            int j = idx >> 3, c4 = (idx & 7) * 4;
            unsigned* d = &Vp[buf][j * 40 + c4];
            d[0] = pack_bf16x2(rv0[i].x, rv1[i].x);
            d[1] = pack_bf16x2(rv0[i].y, rv1[i].y);
            d[2] = pack_bf16x2(rv0[i].z, rv1[i].z);
            d[3] = pack_bf16x2(rv0[i].w, rv1[i].w);
        }
        __syncthreads();

        if (n0 + 64 < KK) {
#pragma unroll
            for (int i = 0; i < 4; i++) {
                int idx = tid + i * 128;
                int r = idx >> 3, c4 = (idx & 7) * 4;
                rk[i] = *(const float4*)(Kb + base + (size_t)(n0 + 64 + r) * CC + c4);
            }
#pragma unroll
            for (int i = 0; i < 2; i++) {
                int idx = tid + i * 128;
                int j = idx >> 3, c4 = (idx & 7) * 4;
                rv0[i] = *(const float4*)(Vb + base + (size_t)(n0 + 64 + 2 * j)     * CC + c4);
                rv1[i] = *(const float4*)(Vb + base + (size_t)(n0 + 64 + 2 * j + 1) * CC + c4);
            }
        }

        float s[8][4];
#pragma unroll
        for (int nt = 0; nt < 8; nt++) {
            s[nt][0] = s[nt][1] = s[nt][2] = s[nt][3] = 0.f;
        }
#pragma unroll
        for (int kc = 0; kc < 2; kc++) {
#pragma unroll
            for (int nt = 0; nt < 8; nt++) {
                int n = nt * 8 + grp;
                unsigned kb0 = Kbf[buf][n * 20 + kc * 8 + tig];
                unsigned kb1 = Kbf[buf][n * 20 + kc * 8 + tig + 4];
                mma_bf16(s[nt], qf[kc][0], qf[kc][1], qf[kc][2], qf[kc][3], kb0, kb1);
            }
        }

        float tm0 = -INFINITY, tm1 = -INFINITY;
#pragma unroll
        for (int nt = 0; nt < 8; nt++) {
            tm0 = fmaxf(tm0, fmaxf(s[nt][0], s[nt][1]));
            tm1 = fmaxf(tm1, fmaxf(s[nt][2], s[nt][3]));
        }
        tm0 = fmaxf(tm0, __shfl_xor_sync(0xffffffff, tm0, 1));
        tm0 = fmaxf(tm0, __shfl_xor_sync(0xffffffff, tm0, 2));
        tm1 = fmaxf(tm1, __shfl_xor_sync(0xffffffff, tm1, 1));
        tm1 = fmaxf(tm1, __shfl_xor_sync(0xffffffff, tm1, 2));

        float mn0 = fmaxf(mr0, tm0), mn1 = fmaxf(mr1, tm1);
        float corr0 = __expf(mr0 - mn0), corr1 = __expf(mr1 - mn1);
        float ps0 = 0.f, ps1 = 0.f;
#pragma unroll
        for (int nt = 0; nt < 8; nt++) {
            float p0 = __expf(s[nt][0] - mn0);
            float p1 = __expf(s[nt][1] - mn0);
            float p2 = __expf(s[nt][2] - mn1);
            float p3 = __expf(s[nt][3] - mn1);
            ps0 += p0 + p1; ps1 += p2 + p3;
            int cp = nt * 4 + tig;
            Pp[(wr + grp) * 36 + cp]     = pack_bf16x2(p0, p1);
            Pp[(wr + grp + 8) * 36 + cp] = pack_bf16x2(p2, p3);
        }
        ps0 += __shfl_xor_sync(0xffffffff, ps0, 1);
        ps0 += __shfl_xor_sync(0xffffffff, ps0, 2);
        ps1 += __shfl_xor_sync(0xffffffff, ps1, 1);
        ps1 += __shfl_xor_sync(0xffffffff, ps1, 2);
        l0 = l0 * corr0 + ps0;
        l1 = l1 * corr1 + ps1;
#pragma unroll
        for (int dt = 0; dt < 4; dt++) {
            oacc[dt][0] *= corr0; oacc[dt][1] *= corr0;
            oacc[dt][2] *= corr1; oacc[dt][3] *= corr1;
        }
        mr0 = mn0; mr1 = mn1;
        __syncwarp();

#pragma unroll
        for (int kc = 0; kc < 4; kc++) {
            unsigned a0 = Pp[(wr + grp) * 36 + kc * 8 + tig];
            unsigned a1 = Pp[(wr + grp + 8) * 36 + kc * 8 + tig];
            unsigned a2 = Pp[(wr + grp) * 36 + kc * 8 + tig + 4];
            unsigned a3 = Pp[(wr + grp + 8) * 36 + kc * 8 + tig + 4];
#pragma unroll
            for (int dt = 0; dt < 4; dt++) {
                unsigned vb0 = Vp[buf][(kc * 8 + tig) * 40 + dt * 8 + grp];
                unsigned vb1 = Vp[buf][(kc * 8 + tig + 4) * 40 + dt * 8 + grp];
                mma_bf16(oacc[dt], a0, a1, a2, a3, vb0, vb1);
            }
        }
        __syncwarp();
    }

    const float inv0 = 1.0f / l0, inv1 = 1.0f / l1;
    const int row = m0 + wr + grp;
#pragma unroll
    for (int dt = 0; dt < 4; dt++) {
        int col = dt * 8 + tig * 2;
        float2 o0 = { oacc[dt][0] * inv0, oacc[dt][1] * inv0 };
        float2 o1 = { oacc[dt][2] * inv1, oacc[dt][3] * inv1 };
        *(float2*)(O + base + (size_t)row * CC + col)       = o0;
        *(float2*)(O + base + (size_t)(row + 8) * CC + col) = o1;
    }
}

// ===== kernel 6: residual + LayerNorm =====
__global__ void ln_kernel(const float* __restrict__ P,
                          const float* __restrict__ X,
                          const float* __restrict__ g,
                          const float* __restrict__ beta,
                          float* __restrict__ E)
{
    const int row = blockIdx.x;
    const int c = threadIdx.x;
    const size_t off = (size_t)row * CC + c;
    float y = P[off] + X[off];
    float v1 = y, v2 = y * y;
#pragma unroll
    for (int o = 16; o > 0; o >>= 1) {
        v1 += __shfl_xor_sync(0xffffffff, v1, o);
        v2 += __shfl_xor_sync(0xffffffff, v2, o);
    }
    __shared__ float s1[8], s2[8];
    int w = c >> 5, ln = c & 31;
    if (ln == 0) { s1[w] = v1; s2[w] = v2; }
    __syncthreads();
    float sum = 0.f, sq = 0.f;
#pragma unroll
    for (int i = 0; i < 8; i++) { sum += s1[i]; sq += s2[i]; }
    float mu  = sum * (1.0f / CC);
    float var = sq * (1.0f / CC) - mu * mu;
    float rs  = rsqrtf(var + 1e-5f);
    E[off] = (y - mu) * rs * g[c] + beta[c];
}

// ===== kernel 7: output assembly (x everywhere; enhanced at selected tokens) =====
__global__ void scatter_kernel(const float* __restrict__ X,
                               const int* __restrict__ pos2k,
                               const float* __restrict__ E,
                               float* __restrict__ out)
{
    const int gid = blockIdx.x * 256 + threadIdx.x;
    const int b = gid >> 20;
    const int c = (gid >> 12) & (CC - 1);
    const int p = gid & (NN - 1);
    int k = pos2k[(b << 12) + p];
    out[gid] = (k >= 0) ? E[(size_t)(((b << 10) + k) << 8) + c] : X[gid];
}

// ===== host launch =====
extern "C" void kernel_launch(void* const* d_in, const int* in_sizes, int n_in,
                              void* d_out, int out_size)
{
    const float* x    = (const float*)d_in[0];
    const float* bmap = (const float*)d_in[1];
    const float* iw1  = (const float*)d_in[2];
    const float* ib1  = (const float*)d_in[3];
    const float* iw2  = (const float*)d_in[4];
    const float* ib2  = (const float*)d_in[5];
    const float* wq   = (const float*)d_in[6];
    const float* bq   = (const float*)d_in[7];
    const float* wk   = (const float*)d_in[8];
    const float* bk   = (const float*)d_in[9];
    const float* wv   = (const float*)d_in[10];
    const float* bv   = (const float*)d_in[11];
    const float* wo   = (const float*)d_in[12];
    const float* bo   = (const float*)d_in[13];
    const float* lng  = (const float*)d_in[14];
    const float* lnb  = (const float*)d_in[15];

    static float *P_imp = nullptr, *P_xsp, *P_q, *P_k, *P_v, *P_ao, *P_ps, *P_enh;
    static int *P_topidx, *P_pos2k;
    if (!P_imp) {
        cudaGetSymbolAddress((void**)&P_imp,    g_imp);
        cudaGetSymbolAddress((void**)&P_topidx, g_topidx);
        cudaGetSymbolAddress((void**)&P_pos2k,  g_pos2k);
        cudaGetSymbolAddress((void**)&P_xsp,    g_xsp);
        cudaGetSymbolAddress((void**)&P_q,      g_q);
        cudaGetSymbolAddress((void**)&P_k,      g_k);
        cudaGetSymbolAddress((void**)&P_v,      g_v);
        cudaGetSymbolAddress((void**)&P_ao,     g_ao);
        cudaGetSymbolAddress((void**)&P_ps,     g_ps);
        cudaGetSymbolAddress((void**)&P_enh,    g_enh);
    }

    float* out = (float*)d_out;
    float* imp_out = (out_size >= BB * CC * NN + BB * NN) ? out + (size_t)BB * CC * NN
                                                          : nullptr;

    importance_mma_kernel<<<BB * 32, 256>>>(x, bmap, iw1, ib1, iw2, ib2,
                                            P_imp, imp_out);
    topk_kernel<<<BB, 1024>>>(P_imp, P_topidx, P_pos2k);

    dim3 grid_gather(KK / 32, CC / 32, BB);
    gather_kernel<<<grid_gather, 256>>>(x, P_topidx, P_xsp);

    dim3 grid_qkv(CC / 64, (BB * KK) / 128, 3);
    gemm_f16_kernel<<<grid_qkv, 256>>>(P_xsp,
                                       wq, bq, P_q,
                                       wk, bk, P_k,
                                       wv, bv, P_v,
                                       BB * KK, CC, CC);

    dim3 grid_attn(KK / 64, NH, BB);
    attn_bf16_kernel<<<grid_attn, 128>>>(P_q, P_k, P_v, P_ao);

    dim3 grid_o(CC / 64, (BB * KK) / 128, 1);
    gemm_f16_kernel<<<grid_o, 256>>>(P_ao,
                                     wo, bo, P_ps,
                                     wo, bo, P_ps,
                                     wo, bo, P_ps,
                                     BB * KK, CC, CC);

    ln_kernel<<<BB * KK, 256>>>(P_ps, P_xsp, lng, lnb, P_enh);
    scatter_kernel<<<(BB * CC * NN) / 256, 256>>>(x, P_pos2k, P_enh, out);
}